// round 7
// baseline (speedup 1.0000x reference)
#include <cuda_runtime.h>
#include <cuda_bf16.h>
#include <math.h>
#include <stdint.h>

#define Bb   64
#define Nn   1024
#define DIN  32
#define DOUT 64
#define CIN  96
#define KSUP 3
#define EDm  16
#define OG   128
#define OU   64
#define KI   288

// fp32 scratch
__device__ float g_Wg [(size_t)Nn * KI * OG];
__device__ float g_Wu [(size_t)Nn * KI * OU];
__device__ float g_bg [(size_t)Nn * OG];
__device__ float g_bu [(size_t)Nn * OU];
__device__ float g_Lt [(size_t)Nn * Nn];
__device__ float g_XG [(size_t)Bb * Nn * KI];
__device__ float g_Ucm[(size_t)Bb * CIN * Nn];
__device__ float g_X0 [(size_t)Bb * Nn * OG];
__device__ float g_X0T[(size_t)Bb * OG * Nn];
__device__ float g_G0 [(size_t)Bb * Nn * OG];
__device__ float g_G1 [(size_t)Bb * Nn * OG];
__device__ float g_Rb [(size_t)Bb * Nn * DOUT];
__device__ float g_Y0 [Bb * OG];
__device__ float g_Y1 [Bb * OG];
__device__ float g_s0 [Bb];
__device__ float g_s1 [Bb];
// pre-split bf16 hi/lo (u32 = bf16x2 k-pair)
__device__ uint32_t g_LmH [(size_t)Nn * 512],      g_LmL [(size_t)Nn * 512];
__device__ uint32_t g_LtH [(size_t)Nn * 512],      g_LtL [(size_t)Nn * 512];
__device__ uint32_t g_S2H [(size_t)Nn * 512],      g_S2L [(size_t)Nn * 512];
__device__ uint32_t g_chH [(size_t)3 * Nn * 512],  g_chL [(size_t)3 * Nn * 512];
__device__ uint32_t g_UcmH[(size_t)Bb * CIN * 512], g_UcmL[(size_t)Bb * CIN * 512];
__device__ uint32_t g_X0TH[(size_t)Bb * OG * 512],  g_X0TL[(size_t)Bb * OG * 512];
__device__ uint32_t g_XG1H[(size_t)Bb * Nn * 192],  g_XG1L[(size_t)Bb * Nn * 192];
__device__ uint32_t g_ggwH[OG * 192],  g_ggwL[OG * 192];
__device__ uint32_t g_ugwH[OU * 96],   g_ugwL[OU * 96];

// ---------- helpers ----------
static __device__ __forceinline__ void mma16(float* d, const uint32_t* a,
                                             uint32_t b0, uint32_t b1) {
    asm volatile(
        "mma.sync.aligned.m16n8k16.row.col.f32.bf16.bf16.f32 "
        "{%0,%1,%2,%3}, {%4,%5,%6,%7}, {%8,%9}, {%0,%1,%2,%3};"
        : "+f"(d[0]), "+f"(d[1]), "+f"(d[2]), "+f"(d[3])
        : "r"(a[0]), "r"(a[1]), "r"(a[2]), "r"(a[3]), "r"(b0), "r"(b1));
}
static __device__ __forceinline__ uint32_t packbf(float x, float y) {
    __nv_bfloat162 h = __floats2bfloat162_rn(x, y);
    return *reinterpret_cast<uint32_t*>(&h);
}
static __device__ __forceinline__ void split2(float a, float b, uint32_t& hi, uint32_t& lo) {
    __nv_bfloat16 ha = __float2bfloat16_rn(a), hb = __float2bfloat16_rn(b);
    __nv_bfloat162 p; p.x = ha; p.y = hb;
    hi = *reinterpret_cast<uint32_t*>(&p);
    lo = packbf(a - __bfloat162float(ha), b - __bfloat162float(hb));
}
static __device__ __forceinline__ void split4(float4 v, uint2& hi, uint2& lo) {
    split2(v.x, v.y, hi.x, lo.x);
    split2(v.z, v.w, hi.y, lo.y);
}

#define RSTR 20   // smem row stride in u32

// ---------- pre-split bf16x3 GEMM: D[m,n] = alpha*sum_k A[m,k]B[n,k] (+bias) (-I) ------
// A,B given as hi/lo u32 (bf16x2 per k-pair), row strides in u32. Output: fp32 C, or
// split CHi/CLo when CHi != nullptr. M%128==0, N=NT*grid.x, K%32==0, batch=grid.z.
template <int NT>
__global__ __launch_bounds__(256, 1) void mma_gemm_sp(
    const uint32_t* __restrict__ Ahi, const uint32_t* __restrict__ Alo, int ldaU, long sAU,
    const uint32_t* __restrict__ Bhi, const uint32_t* __restrict__ Blo, int ldbU, long sBU,
    float* __restrict__ C, int ldc, long sC,
    uint32_t* __restrict__ CHi, uint32_t* __restrict__ CLo, int ldcU, long sCU,
    int K, const float* __restrict__ bias, float alpha, int minusI)
{
    constexpr int NTILES = NT / 16;
    constexpr int NB4 = (NT * 4 + 255) / 256;      // uint4 iters for B
    constexpr int AROWS_U32 = 128 * RSTR;
    constexpr int BROWS_U32 = NT * RSTR;
    constexpr int STG = 2 * AROWS_U32 + 2 * BROWS_U32;

    extern __shared__ uint32_t dsm[];

    Ahi += (long)blockIdx.z * sAU; Alo += (long)blockIdx.z * sAU;
    Bhi += (long)blockIdx.z * sBU; Blo += (long)blockIdx.z * sBU;
    const int m0 = blockIdx.y * 128, n0 = blockIdx.x * NT;
    const int tid = threadIdx.x, wid = tid >> 5, lid = tid & 31;
    const int g = lid >> 2, t = lid & 3;
    const int wm = (wid & 3) * 32, wn = (wid >> 2) * (NT / 2);

    const uint32_t* AhiG = Ahi + (long)m0 * ldaU;
    const uint32_t* AloG = Alo + (long)m0 * ldaU;
    const uint32_t* BhiG = Bhi + (long)n0 * ldbU;
    const uint32_t* BloG = Blo + (long)n0 * ldbU;

    float acc[2][NTILES][4];
    #pragma unroll
    for (int i = 0; i < 2; i++)
        #pragma unroll
        for (int j = 0; j < NTILES; j++)
            #pragma unroll
            for (int q = 0; q < 4; q++) acc[i][j][q] = 0.f;

    const int nch = K >> 5;
    uint4 paH[2], paL[2], pbH[NB4], pbL[NB4];

    // prologue: chunk 0
    #pragma unroll
    for (int i = 0; i < 2; i++) {
        int f = i * 256 + tid, row = f >> 2, q = (f & 3) << 2;
        paH[i] = *(const uint4*)(AhiG + (long)row * ldaU + q);
        paL[i] = *(const uint4*)(AloG + (long)row * ldaU + q);
    }
    #pragma unroll
    for (int i = 0; i < NB4; i++) {
        int f = i * 256 + tid;
        if (f < NT * 4) {
            int row = f >> 2, q = (f & 3) << 2;
            pbH[i] = *(const uint4*)(BhiG + (long)row * ldbU + q);
            pbL[i] = *(const uint4*)(BloG + (long)row * ldbU + q);
        }
    }
    {
        uint32_t* Ah = dsm;                 uint32_t* Al = dsm + AROWS_U32;
        uint32_t* Bh = dsm + 2 * AROWS_U32; uint32_t* Bl = Bh + BROWS_U32;
        #pragma unroll
        for (int i = 0; i < 2; i++) {
            int f = i * 256 + tid, row = f >> 2, q = (f & 3) << 2;
            *(uint4*)(Ah + row * RSTR + q) = paH[i];
            *(uint4*)(Al + row * RSTR + q) = paL[i];
        }
        #pragma unroll
        for (int i = 0; i < NB4; i++) {
            int f = i * 256 + tid;
            if (f < NT * 4) {
                int row = f >> 2, q = (f & 3) << 2;
                *(uint4*)(Bh + row * RSTR + q) = pbH[i];
                *(uint4*)(Bl + row * RSTR + q) = pbL[i];
            }
        }
    }
    __syncthreads();

    for (int c = 0; c < nch; c++) {
        if (c + 1 < nch) {
            const int kp = (c + 1) << 4;
            #pragma unroll
            for (int i = 0; i < 2; i++) {
                int f = i * 256 + tid, row = f >> 2, q = (f & 3) << 2;
                paH[i] = *(const uint4*)(AhiG + (long)row * ldaU + kp + q);
                paL[i] = *(const uint4*)(AloG + (long)row * ldaU + kp + q);
            }
            #pragma unroll
            for (int i = 0; i < NB4; i++) {
                int f = i * 256 + tid;
                if (f < NT * 4) {
                    int row = f >> 2, q = (f & 3) << 2;
                    pbH[i] = *(const uint4*)(BhiG + (long)row * ldbU + kp + q);
                    pbL[i] = *(const uint4*)(BloG + (long)row * ldbU + kp + q);
                }
            }
        }

        {
            const uint32_t* base = dsm + (c & 1) * STG;
            const uint32_t* Ah = base;                 const uint32_t* Al = base + AROWS_U32;
            const uint32_t* Bh = base + 2 * AROWS_U32; const uint32_t* Bl = Bh + BROWS_U32;
            #pragma unroll
            for (int s = 0; s < 2; s++) {
                uint32_t ah[2][4], al[2][4];
                #pragma unroll
                for (int mt = 0; mt < 2; mt++) {
                    int r = (wm + mt * 16 + g) * RSTR + s * 8 + t;
                    ah[mt][0] = Ah[r];     ah[mt][1] = Ah[r + 8 * RSTR];
                    ah[mt][2] = Ah[r + 4]; ah[mt][3] = Ah[r + 8 * RSTR + 4];
                    al[mt][0] = Al[r];     al[mt][1] = Al[r + 8 * RSTR];
                    al[mt][2] = Al[r + 4]; al[mt][3] = Al[r + 8 * RSTR + 4];
                }
                #pragma unroll
                for (int nt = 0; nt < NTILES; nt++) {
                    int bo = (wn + nt * 8 + g) * RSTR + s * 8 + t;
                    uint32_t bh0 = Bh[bo], bh1 = Bh[bo + 4];
                    uint32_t bl0 = Bl[bo], bl1 = Bl[bo + 4];
                    #pragma unroll
                    for (int mt = 0; mt < 2; mt++) {
                        mma16(acc[mt][nt], ah[mt], bh0, bh1);
                        mma16(acc[mt][nt], al[mt], bh0, bh1);
                        mma16(acc[mt][nt], ah[mt], bl0, bl1);
                    }
                }
            }
        }

        if (c + 1 < nch) {
            uint32_t* base = dsm + ((c + 1) & 1) * STG;
            uint32_t* Ah = base;                 uint32_t* Al = base + AROWS_U32;
            uint32_t* Bh = base + 2 * AROWS_U32; uint32_t* Bl = Bh + BROWS_U32;
            #pragma unroll
            for (int i = 0; i < 2; i++) {
                int f = i * 256 + tid, row = f >> 2, q = (f & 3) << 2;
                *(uint4*)(Ah + row * RSTR + q) = paH[i];
                *(uint4*)(Al + row * RSTR + q) = paL[i];
            }
            #pragma unroll
            for (int i = 0; i < NB4; i++) {
                int f = i * 256 + tid;
                if (f < NT * 4) {
                    int row = f >> 2, q = (f & 3) << 2;
                    *(uint4*)(Bh + row * RSTR + q) = pbH[i];
                    *(uint4*)(Bl + row * RSTR + q) = pbL[i];
                }
            }
            __syncthreads();
        }
    }

    // ---- epilogue ----
    #pragma unroll
    for (int mt = 0; mt < 2; mt++) {
        int r0 = m0 + wm + mt * 16 + g;
        #pragma unroll
        for (int nt = 0; nt < NTILES; nt++) {
            int col = n0 + wn + nt * 8 + t * 2;
            float b0 = 0.f, b1 = 0.f;
            if (bias) { b0 = __ldg(&bias[col]); b1 = __ldg(&bias[col + 1]); }
            float d0 = acc[mt][nt][0] * alpha + b0;
            float d1 = acc[mt][nt][1] * alpha + b1;
            float d2 = acc[mt][nt][2] * alpha + b0;
            float d3 = acc[mt][nt][3] * alpha + b1;
            if (minusI) {
                if (r0 == col)         d0 -= 1.0f;
                if (r0 == col + 1)     d1 -= 1.0f;
                if (r0 + 8 == col)     d2 -= 1.0f;
                if (r0 + 8 == col + 1) d3 -= 1.0f;
            }
            if (CHi) {
                long cp = (long)(blockIdx.z) * sCU;
                int pc = col >> 1;
                uint32_t h, l;
                split2(d0, d1, h, l);
                CHi[cp + (long)r0 * ldcU + pc] = h;  CLo[cp + (long)r0 * ldcU + pc] = l;
                split2(d2, d3, h, l);
                CHi[cp + (long)(r0 + 8) * ldcU + pc] = h;  CLo[cp + (long)(r0 + 8) * ldcU + pc] = l;
            } else {
                float* Cb = C + (long)blockIdx.z * sC;
                *(float2*)(Cb + (long)r0 * ldc + col)       = make_float2(d0, d1);
                *(float2*)(Cb + (long)(r0 + 8) * ldc + col) = make_float2(d2, d3);
            }
        }
    }
}

// ---------- fp32-input bf16x3 GEMM (small K: x0) — proven R6 kernel ----------
template <int NT>
__global__ __launch_bounds__(256, 1) void mma_gemm_f32(
    const float* __restrict__ A, int lda, long sA,
    const float* __restrict__ Bm, int ldb, long sB,
    float* __restrict__ C, int ldc, long sC,
    int K, const float* __restrict__ bias, float alpha)
{
    constexpr int NTILES = NT / 16;
    constexpr int NB = NT / 32;
    constexpr int AROWS_U32 = 128 * RSTR;
    constexpr int BROWS_U32 = NT * RSTR;
    constexpr int STG = 2 * AROWS_U32 + 2 * BROWS_U32;
    extern __shared__ uint32_t dsm[];
    A += (long)blockIdx.z * sA; Bm += (long)blockIdx.z * sB; C += (long)blockIdx.z * sC;
    const int m0 = blockIdx.y * 128, n0 = blockIdx.x * NT;
    const int tid = threadIdx.x, wid = tid >> 5, lid = tid & 31;
    const int g = lid >> 2, t = lid & 3;
    const int wm = (wid & 3) * 32, wn = (wid >> 2) * (NT / 2);
    const float* Ag = A + (long)m0 * lda;
    const float* Bg = Bm + (long)n0 * ldb;
    float acc[2][NTILES][4];
    #pragma unroll
    for (int i = 0; i < 2; i++)
        #pragma unroll
        for (int j = 0; j < NTILES; j++)
            #pragma unroll
            for (int q = 0; q < 4; q++) acc[i][j][q] = 0.f;
    const int nch = K >> 5;
    for (int c = 0; c < nch; c++) {
        uint32_t* base = dsm + 0;
        uint32_t* Ah = base;                 uint32_t* Al = base + AROWS_U32;
        uint32_t* Bh = base + 2 * AROWS_U32; uint32_t* Bl = Bh + BROWS_U32;
        const int k0 = c << 5;
        if (c) __syncthreads();
        #pragma unroll
        for (int i = 0; i < 4; i++) {
            int f = i * 256 + tid, row = f >> 3, q = f & 7;
            float4 v = *(const float4*)(Ag + (long)row * lda + k0 + (q << 2));
            uint2 hi, lo; split4(v, hi, lo);
            *(uint2*)(Ah + row * RSTR + 2 * q) = hi;
            *(uint2*)(Al + row * RSTR + 2 * q) = lo;
        }
        #pragma unroll
        for (int i = 0; i < NB; i++) {
            int f = i * 256 + tid, row = f >> 3, q = f & 7;
            float4 v = *(const float4*)(Bg + (long)row * ldb + k0 + (q << 2));
            uint2 hi, lo; split4(v, hi, lo);
            *(uint2*)(Bh + row * RSTR + 2 * q) = hi;
            *(uint2*)(Bl + row * RSTR + 2 * q) = lo;
        }
        __syncthreads();
        #pragma unroll
        for (int s = 0; s < 2; s++) {
            uint32_t ah[2][4], al[2][4];
            #pragma unroll
            for (int mt = 0; mt < 2; mt++) {
                int r = (wm + mt * 16 + g) * RSTR + s * 8 + t;
                ah[mt][0] = Ah[r];     ah[mt][1] = Ah[r + 8 * RSTR];
                ah[mt][2] = Ah[r + 4]; ah[mt][3] = Ah[r + 8 * RSTR + 4];
                al[mt][0] = Al[r];     al[mt][1] = Al[r + 8 * RSTR];
                al[mt][2] = Al[r + 4]; al[mt][3] = Al[r + 8 * RSTR + 4];
            }
            #pragma unroll
            for (int nt = 0; nt < NTILES; nt++) {
                int bo = (wn + nt * 8 + g) * RSTR + s * 8 + t;
                uint32_t bh0 = Bh[bo], bh1 = Bh[bo + 4];
                uint32_t bl0 = Bl[bo], bl1 = Bl[bo + 4];
                #pragma unroll
                for (int mt = 0; mt < 2; mt++) {
                    mma16(acc[mt][nt], ah[mt], bh0, bh1);
                    mma16(acc[mt][nt], al[mt], bh0, bh1);
                    mma16(acc[mt][nt], ah[mt], bl0, bl1);
                }
            }
        }
    }
    #pragma unroll
    for (int mt = 0; mt < 2; mt++) {
        int r0 = m0 + wm + mt * 16 + g;
        #pragma unroll
        for (int nt = 0; nt < NTILES; nt++) {
            int col = n0 + wn + nt * 8 + t * 2;
            float b0 = 0.f, b1 = 0.f;
            if (bias) { b0 = __ldg(&bias[col]); b1 = __ldg(&bias[col + 1]); }
            *(float2*)(C + (long)r0 * ldc + col) =
                make_float2(acc[mt][nt][0] * alpha + b0, acc[mt][nt][1] * alpha + b1);
            *(float2*)(C + (long)(r0 + 8) * ldc + col) =
                make_float2(acc[mt][nt][2] * alpha + b0, acc[mt][nt][3] * alpha + b1);
        }
    }
}

// ---------- per-node dynamic-weight contraction (SIMT fp32, proven) ----------
template <int O>
__global__ __launch_bounds__(256) void pernode_gconv(
    const float* __restrict__ XG, const float* __restrict__ W,
    const float* __restrict__ bias, float* __restrict__ out)
{
    constexpr int TN = O / 16;
    const int n = blockIdx.x, tid = threadIdx.x;
    const int trow = tid >> 4, tcol = tid & 15;
    __shared__ float As[64][33];
    __shared__ float Ws[32][O];
    const float* Wn = W + (long)n * KI * O;
    float acc[4][TN];
    #pragma unroll
    for (int i = 0; i < 4; i++)
        #pragma unroll
        for (int j = 0; j < TN; j++) acc[i][j] = 0.f;
    const int lb = tid >> 2, lk = (tid & 3) * 8;
    for (int k0 = 0; k0 < KI; k0 += 32) {
        const float* src = XG + ((long)lb * Nn + n) * KI + k0 + lk;
        float4 v0 = *(const float4*)(src);
        float4 v1 = *(const float4*)(src + 4);
        As[lb][lk + 0] = v0.x; As[lb][lk + 1] = v0.y; As[lb][lk + 2] = v0.z; As[lb][lk + 3] = v0.w;
        As[lb][lk + 4] = v1.x; As[lb][lk + 5] = v1.y; As[lb][lk + 6] = v1.z; As[lb][lk + 7] = v1.w;
        const float* wsrc = Wn + (long)k0 * O;
        #pragma unroll
        for (int i = tid * 4; i < 32 * O; i += 1024)
            *(float4*)(&Ws[0][0] + i) = *(const float4*)(wsrc + i);
        __syncthreads();
        #pragma unroll
        for (int k = 0; k < 32; k++) {
            float a0 = As[trow * 4 + 0][k], a1 = As[trow * 4 + 1][k];
            float a2 = As[trow * 4 + 2][k], a3 = As[trow * 4 + 3][k];
            #pragma unroll
            for (int j = 0; j < TN; j++) {
                float w = Ws[k][tcol + 16 * j];
                acc[0][j] += a0 * w; acc[1][j] += a1 * w;
                acc[2][j] += a2 * w; acc[3][j] += a3 * w;
            }
        }
        __syncthreads();
    }
    #pragma unroll
    for (int i = 0; i < 4; i++) {
        int b = trow * 4 + i;
        #pragma unroll
        for (int j = 0; j < TN; j++) {
            int o = tcol + 16 * j;
            out[((long)b * Nn + n) * O + o] = acc[i][j] + bias[(long)n * O + o];
        }
    }
}

// ---------- small kernels ----------
static __device__ __forceinline__ float lrelu(float v) { return v >= 0.0f ? v : 0.01f * v; }
static __device__ __forceinline__ float sigmoidf(float v) { return 1.0f / (1.0f + expf(-v)); }

__global__ void convert_split(const float* __restrict__ in, uint32_t* __restrict__ hi,
                              uint32_t* __restrict__ lo, long npairs)
{
    long i = (long)blockIdx.x * blockDim.x + threadIdx.x;
    if (i >= npairs) return;
    float2 v = ((const float2*)in)[i];
    uint32_t h, l;
    split2(v.x, v.y, h, l);
    hi[i] = h; lo[i] = l;
}

__global__ void emb_matmul2(const float* __restrict__ emb, const float* __restrict__ pool,
                            float* __restrict__ out, int C)
{
    __shared__ float esm[32][EDm];
    const int tid = threadIdx.x;
    const int cb = blockIdx.x * 256 + tid;
    const int n0 = blockIdx.y * 32;
    for (int i = tid; i < 32 * EDm; i += 256)
        esm[i >> 4][i & 15] = emb[(n0 + (i >> 4)) * EDm + (i & 15)];
    __syncthreads();
    if (cb >= C) return;
    float p[EDm];
    #pragma unroll
    for (int d = 0; d < EDm; d++) p[d] = pool[(long)d * C + cb];
    #pragma unroll 4
    for (int r = 0; r < 32; r++) {
        float acc = 0.f;
        #pragma unroll
        for (int d = 0; d < EDm; d++) acc += esm[r][d] * p[d];
        out[(long)(n0 + r) * C + cb] = acc;
    }
}

__global__ void transpose_batched(const float* __restrict__ in, long s_in, int ld_in,
                                  float* __restrict__ out, long s_out, int ld_out,
                                  int R, int Cc)
{
    __shared__ float tsm[32][33];
    in  += (long)blockIdx.z * s_in;
    out += (long)blockIdx.z * s_out;
    int r0 = blockIdx.x * 32, c0 = blockIdx.y * 32;
    int c = c0 + threadIdx.x;
    #pragma unroll
    for (int i = 0; i < 32; i += 8) {
        int rr = r0 + threadIdx.y + i;
        if (rr < R && c < Cc) tsm[threadIdx.y + i][threadIdx.x] = in[(long)rr * ld_in + c];
    }
    __syncthreads();
    int rr = r0 + threadIdx.x;
    #pragma unroll
    for (int i = 0; i < 32; i += 8) {
        int cc = c0 + threadIdx.y + i;
        if (cc < Cc && rr < R) out[(long)cc * ld_out + rr] = tsm[threadIdx.x][threadIdx.y + i];
    }
}

__global__ void build_xg0(const float* __restrict__ x, const float* __restrict__ st,
                          float* __restrict__ XG)
{
    long idx = (long)blockIdx.x * blockDim.x + threadIdx.x;
    if (idx >= (long)Bb * Nn * CIN) return;
    int c = (int)(idx % CIN);
    long bn = idx / CIN;
    XG[bn * KI + c] = (c < DIN) ? x[bn * DIN + c] : st[bn * DOUT + (c - DIN)];
}

__global__ void colmean_lrelu(const float* __restrict__ G, float* __restrict__ Y, int C)
{
    int b = blockIdx.x, c = threadIdx.x;
    const float* p = G + (long)b * Nn * C + c;
    float a0 = 0.f, a1 = 0.f, a2 = 0.f, a3 = 0.f;
    for (int n = 0; n < Nn; n += 4) {
        a0 += lrelu(p[(long)(n + 0) * C]); a1 += lrelu(p[(long)(n + 1) * C]);
        a2 += lrelu(p[(long)(n + 2) * C]); a3 += lrelu(p[(long)(n + 3) * C]);
    }
    Y[b * C + c] = (a0 + a1 + a2 + a3) * (1.0f / (float)Nn);
}

__global__ void att_scalar(const float* __restrict__ Y, const float* __restrict__ w1,
                           const float* __restrict__ w2, float* __restrict__ s, int C, int H)
{
    int b = blockIdx.x, j = threadIdx.x;
    float h = 0.f;
    if (j < H) {
        float acc = 0.f;
        for (int c = 0; c < C; c++) acc += Y[b * C + c] * w1[j * C + c];
        h = fmaxf(acc, 0.f) * w2[j];
    }
    #pragma unroll
    for (int off = 16; off; off >>= 1) h += __shfl_down_sync(0xffffffffu, h, off);
    if (j == 0) s[b] = sigmoidf(h);
}

__global__ void gate_combine(const float* __restrict__ G0, const float* __restrict__ G1,
                             const float* __restrict__ s0, const float* __restrict__ s1,
                             const float* __restrict__ x, const float* __restrict__ st,
                             float* __restrict__ XG, float* __restrict__ Rb)
{
    long idx = (long)blockIdx.x * blockDim.x + threadIdx.x;
    if (idx >= (long)Bb * Nn * DOUT) return;
    int o = (int)(idx % DOUT);
    long bn = idx / DOUT;
    int b = (int)(bn >> 10);
    float a0 = s0[b], a1 = s1[b];
    float zi = lrelu(G0[bn * OG + o]) * a0 + lrelu(G1[bn * OG + o]) * a1;
    float ri = lrelu(G0[bn * OG + DOUT + o]) * a0 + lrelu(G1[bn * OG + DOUT + o]) * a1;
    float r = sigmoidf(ri);
    Rb[idx] = r;
    XG[bn * KI + DIN + o] = sigmoidf(zi) * st[idx];
    if (o < DIN) XG[bn * KI + o] = x[bn * DIN + o];
}

__global__ void final_combine(const float* __restrict__ G0u, const float* __restrict__ G1u,
                              const float* __restrict__ t0, const float* __restrict__ t1,
                              const float* __restrict__ Rb, const float* __restrict__ st,
                              float* __restrict__ out)
{
    long idx = (long)blockIdx.x * blockDim.x + threadIdx.x;
    if (idx >= (long)Bb * Nn * DOUT) return;
    long bn = idx / DOUT;
    int b = (int)(bn >> 10);
    float hc = tanhf(lrelu(G0u[idx]) * t0[b] + lrelu(G1u[idx]) * t1[b]);
    float r = Rb[idx];
    out[idx] = r * st[idx] + (1.0f - r) * hc;
}

// ---------- host ----------
static inline int gemm_smem(int NT) { return 2 * (2 * 128 * RSTR + 2 * NT * RSTR) * 4; }

struct SpArgs {
    const uint32_t *Ah, *Al; int ldaU; long sAU;
    const uint32_t *Bh, *Bl; int ldbU; long sBU;
    float* C; int ldc; long sC;
    uint32_t *CHi, *CLo; int ldcU; long sCU;
    int K; const float* bias; float alpha; int mI;
};
static inline void sp(int M, int N, int NT, int batch, const SpArgs& a)
{
    dim3 grid(N / NT, M / 128, batch);
    int sm = gemm_smem(NT);
    switch (NT) {
    case 128:
        cudaFuncSetAttribute(mma_gemm_sp<128>, cudaFuncAttributeMaxDynamicSharedMemorySize, sm);
        mma_gemm_sp<128><<<grid, 256, sm>>>(a.Ah, a.Al, a.ldaU, a.sAU, a.Bh, a.Bl, a.ldbU, a.sBU,
            a.C, a.ldc, a.sC, a.CHi, a.CLo, a.ldcU, a.sCU, a.K, a.bias, a.alpha, a.mI);
        break;
    case 96:
        cudaFuncSetAttribute(mma_gemm_sp<96>, cudaFuncAttributeMaxDynamicSharedMemorySize, sm);
        mma_gemm_sp<96><<<grid, 256, sm>>>(a.Ah, a.Al, a.ldaU, a.sAU, a.Bh, a.Bl, a.ldbU, a.sBU,
            a.C, a.ldc, a.sC, a.CHi, a.CLo, a.ldcU, a.sCU, a.K, a.bias, a.alpha, a.mI);
        break;
    default:
        cudaFuncSetAttribute(mma_gemm_sp<64>, cudaFuncAttributeMaxDynamicSharedMemorySize, sm);
        mma_gemm_sp<64><<<grid, 256, sm>>>(a.Ah, a.Al, a.ldaU, a.sAU, a.Bh, a.Bl, a.ldbU, a.sBU,
            a.C, a.ldc, a.sC, a.CHi, a.CLo, a.ldcU, a.sCU, a.K, a.bias, a.alpha, a.mI);
        break;
    }
}
static inline void f32gemm(const float* A, int lda, const float* Bm, int ldb,
                           float* C, int ldc, int M, int N, int NT, int K, const float* bias)
{
    dim3 grid(N / NT, M / 128, 1);
    int sm = gemm_smem(NT);
    if (NT == 128) {
        cudaFuncSetAttribute(mma_gemm_f32<128>, cudaFuncAttributeMaxDynamicSharedMemorySize, sm);
        mma_gemm_f32<128><<<grid, 256, sm>>>(A, lda, 0, Bm, ldb, 0, C, ldc, 0, K, bias, 1.0f);
    } else {
        cudaFuncSetAttribute(mma_gemm_f32<64>, cudaFuncAttributeMaxDynamicSharedMemorySize, sm);
        mma_gemm_f32<64><<<grid, 256, sm>>>(A, lda, 0, Bm, ldb, 0, C, ldc, 0, K, bias, 1.0f);
    }
}
static inline void csplit(const float* in, uint32_t* hi, uint32_t* lo, long npairs)
{
    convert_split<<<(npairs + 255) / 256, 256>>>(in, hi, lo, npairs);
}

extern "C" void kernel_launch(void* const* d_in, const int* in_sizes, int n_in,
                              void* d_out, int out_size)
{
    const float* x     = (const float*)d_in[0];
    const float* state = (const float*)d_in[1];
    const float* emb   = (const float*)d_in[2];
    const float* Lm    = (const float*)d_in[3];
    const float* cheb  = (const float*)d_in[4];
    const float* gwpool = (const float*)d_in[5];
    const float* gbpool = (const float*)d_in[6];
    const float* giw = (const float*)d_in[7];
    const float* gib = (const float*)d_in[8];
    const float* ggw = (const float*)d_in[9];
    const float* ggb = (const float*)d_in[10];
    const float* ga1w1 = (const float*)d_in[11];
    const float* ga1w2 = (const float*)d_in[12];
    const float* ga2w1 = (const float*)d_in[13];
    const float* ga2w2 = (const float*)d_in[14];
    const float* uwpool = (const float*)d_in[15];
    const float* ubpool = (const float*)d_in[16];
    const float* uiw = (const float*)d_in[17];
    const float* uib = (const float*)d_in[18];
    const float* ugw = (const float*)d_in[19];
    const float* ugb = (const float*)d_in[20];
    const float* ua1w1 = (const float*)d_in[21];
    const float* ua1w2 = (const float*)d_in[22];
    const float* ua2w1 = (const float*)d_in[23];
    const float* ua2w2 = (const float*)d_in[24];
    float* out = (float*)d_out;

    float *Wg, *Wu, *bg, *bu, *Lt, *XG, *Ucm, *X0, *X0T, *G0, *G1, *Rb, *Y0, *Y1, *s0, *s1;
    uint32_t *LmH, *LmL, *LtH, *LtL, *S2H, *S2L, *chH, *chL, *UcmH, *UcmL;
    uint32_t *X0TH, *X0TL, *XG1H, *XG1L, *ggwH, *ggwL, *ugwH, *ugwL;
    cudaGetSymbolAddress((void**)&Wg, g_Wg);   cudaGetSymbolAddress((void**)&Wu, g_Wu);
    cudaGetSymbolAddress((void**)&bg, g_bg);   cudaGetSymbolAddress((void**)&bu, g_bu);
    cudaGetSymbolAddress((void**)&Lt, g_Lt);   cudaGetSymbolAddress((void**)&XG, g_XG);
    cudaGetSymbolAddress((void**)&Ucm, g_Ucm); cudaGetSymbolAddress((void**)&X0, g_X0);
    cudaGetSymbolAddress((void**)&X0T, g_X0T); cudaGetSymbolAddress((void**)&G0, g_G0);
    cudaGetSymbolAddress((void**)&G1, g_G1);   cudaGetSymbolAddress((void**)&Rb, g_Rb);
    cudaGetSymbolAddress((void**)&Y0, g_Y0);   cudaGetSymbolAddress((void**)&Y1, g_Y1);
    cudaGetSymbolAddress((void**)&s0, g_s0);   cudaGetSymbolAddress((void**)&s1, g_s1);
    cudaGetSymbolAddress((void**)&LmH, g_LmH); cudaGetSymbolAddress((void**)&LmL, g_LmL);
    cudaGetSymbolAddress((void**)&LtH, g_LtH); cudaGetSymbolAddress((void**)&LtL, g_LtL);
    cudaGetSymbolAddress((void**)&S2H, g_S2H); cudaGetSymbolAddress((void**)&S2L, g_S2L);
    cudaGetSymbolAddress((void**)&chH, g_chH); cudaGetSymbolAddress((void**)&chL, g_chL);
    cudaGetSymbolAddress((void**)&UcmH, g_UcmH); cudaGetSymbolAddress((void**)&UcmL, g_UcmL);
    cudaGetSymbolAddress((void**)&X0TH, g_X0TH); cudaGetSymbolAddress((void**)&X0TL, g_X0TL);
    cudaGetSymbolAddress((void**)&XG1H, g_XG1H); cudaGetSymbolAddress((void**)&XG1L, g_XG1L);
    cudaGetSymbolAddress((void**)&ggwH, g_ggwH); cudaGetSymbolAddress((void**)&ggwL, g_ggwL);
    cudaGetSymbolAddress((void**)&ugwH, g_ugwH); cudaGetSymbolAddress((void**)&ugwL, g_ugwL);

    const long sXG = (long)Nn * KI;
    dim3 tb(32, 8);

    // per-node weights / biases
    emb_matmul2<<<dim3(144, 32), 256>>>(emb, gwpool, Wg, KI * OG);
    emb_matmul2<<<dim3(72, 32), 256>>>(emb, uwpool, Wu, KI * OU);
    emb_matmul2<<<dim3(1, 32), 256>>>(emb, gbpool, bg, OG);
    emb_matmul2<<<dim3(1, 32), 256>>>(emb, ubpool, bu, OU);

    // static splits
    transpose_batched<<<dim3(32, 32, 1), tb>>>(Lm, 0, Nn, Lt, 0, Nn, Nn, Nn);
    csplit(Lm, LmH, LmL, (long)Nn * 512);
    csplit(Lt, LtH, LtL, (long)Nn * 512);
    csplit(cheb, chH, chL, (long)3 * Nn * 512);
    csplit(ggw, ggwH, ggwL, OG * 192);
    csplit(ugw, ugwH, ugwL, OU * 96);

    // S2 = 2*L@L - I  -> split output
    {
        SpArgs a = { LmH, LmL, 512, 0, LtH, LtL, 512, 0,
                     nullptr, 0, 0, S2H, S2L, 512, 0, Nn, nullptr, 2.0f, 1 };
        sp(Nn, Nn, 128, 1, a);
    }

    for (int phase = 0; phase < 2; phase++) {
        const int O = phase ? OU : OG;
        // phase 0 input already staged by build_xg0; phase 1 by gate_combine
        if (phase == 0)
            build_xg0<<<((long)Bb * Nn * CIN + 255) / 256, 256>>>(x, state, XG);
        transpose_batched<<<dim3(32, 3, Bb), tb>>>(XG, sXG, KI, Ucm, (long)CIN * Nn, Nn, Nn, CIN);
        csplit(Ucm, UcmH, UcmL, (long)Bb * CIN * 512);
        // diffusion k=1 (L), k=2 (S2)
        {
            SpArgs a = { LmH, LmL, 512, 0, UcmH, UcmL, 512, (long)CIN * 512,
                         XG + CIN, KI, sXG, nullptr, nullptr, 0, 0, Nn, nullptr, 1.0f, 0 };
            sp(Nn, CIN, 96, Bb, a);
            a.Ah = S2H; a.Al = S2L; a.C = XG + 2 * CIN;
            sp(Nn, CIN, 96, Bb, a);
        }
        if (phase == 0) pernode_gconv<OG><<<Nn, 256>>>(XG, Wg, bg, G0);
        else            pernode_gconv<OU><<<Nn, 256>>>(XG, Wu, bu, G0);
        // x0 = U @ iw^T + ib
        f32gemm(XG, KI, phase ? uiw : giw, CIN, X0, O, Bb * Nn, O, phase ? 64 : 128, CIN,
                phase ? uib : gib);
        transpose_batched<<<dim3(32, O / 32, Bb), tb>>>(X0, (long)Nn * O, O,
                                                        X0T, (long)O * Nn, Nn, Nn, O);
        csplit(X0T, X0TH, X0TL, (long)Bb * O * 512);
        // cheb diffusion -> split XG1
        for (int k = 0; k < KSUP; k++) {
            SpArgs a = { chH + (long)k * Nn * 512, chL + (long)k * Nn * 512, 512, 0,
                         X0TH, X0TL, 512, (long)O * 512,
                         nullptr, 0, 0,
                         XG1H + k * (O / 2), XG1L + k * (O / 2), 3 * O / 2, (long)Nn * 3 * O / 2,
                         Nn, nullptr, 1.0f, 0 };
            sp(Nn, O, O == OG ? 128 : 64, Bb, a);
        }
        // gconv1 = XG1 @ gw^T + gb
        {
            SpArgs a = { XG1H, XG1L, 3 * O / 2, 0,
                         phase ? ugwH : ggwH, phase ? ugwL : ggwL, 3 * O / 2, 0,
                         G1, O, 0, nullptr, nullptr, 0, 0,
                         3 * O, phase ? ugb : ggb, 1.0f, 0 };
            sp(Bb * Nn, O, O == OG ? 128 : 64, 1, a);
        }
        colmean_lrelu<<<Bb, O>>>(G0, Y0, O);
        colmean_lrelu<<<Bb, O>>>(G1, Y1, O);
        if (phase == 0) {
            att_scalar<<<Bb, 32>>>(Y0, ga1w1, ga1w2, s0, OG, OG / 16);
            att_scalar<<<Bb, 32>>>(Y1, ga2w1, ga2w2, s1, OG, OG / 16);
            gate_combine<<<((long)Bb * Nn * DOUT + 255) / 256, 256>>>(G0, G1, s0, s1, x, state, XG, Rb);
        } else {
            att_scalar<<<Bb, 32>>>(Y0, ua1w1, ua1w2, s0, OU, OU / 16);
            att_scalar<<<Bb, 32>>>(Y1, ua2w1, ua2w2, s1, OU, OU / 16);
            final_combine<<<((long)Bb * Nn * DOUT + 255) / 256, 256>>>(G0, G1, s0, s1, Rb, state, out);
        }
    }
}

// round 8
// speedup vs baseline: 1.0987x; 1.0987x over previous
#include <cuda_runtime.h>
#include <cuda_bf16.h>
#include <math.h>
#include <stdint.h>

#define Bb   64
#define Nn   1024
#define DIN  32
#define DOUT 64
#define CIN  96
#define KSUP 3
#define EDm  16
#define OG   128
#define OU   64
#define KI   288

__device__ float g_Wg [(size_t)Nn * KI * OG];
__device__ float g_Wu [(size_t)Nn * KI * OU];
__device__ float g_bg [(size_t)Nn * OG];
__device__ float g_bu [(size_t)Nn * OU];
__device__ float g_Lt [(size_t)Nn * Nn];
__device__ float g_S2 [(size_t)Nn * Nn];
__device__ float g_XG [(size_t)Bb * Nn * KI];
__device__ float g_Ucm[(size_t)Bb * CIN * Nn];
__device__ float g_X0 [(size_t)Bb * Nn * OG];
__device__ float g_X0T[(size_t)Bb * OG * Nn];
__device__ float g_XG1[(size_t)Bb * Nn * 3 * OG];
__device__ float g_G0 [(size_t)Bb * Nn * OG];
__device__ float g_G1 [(size_t)Bb * Nn * OG];
__device__ float g_Rb [(size_t)Bb * Nn * DOUT];
__device__ float g_Y0 [Bb * OG];
__device__ float g_Y1 [Bb * OG];
__device__ float g_s0 [Bb];
__device__ float g_s1 [Bb];
// pre-split transposed per-node weights: Wt[n][o][kpair], KI/2 = 144 u32 per row
__device__ uint32_t g_WtgH[(size_t)Nn * OG * (KI / 2)], g_WtgL[(size_t)Nn * OG * (KI / 2)];
__device__ uint32_t g_WtuH[(size_t)Nn * OU * (KI / 2)], g_WtuL[(size_t)Nn * OU * (KI / 2)];

// ---------- mma / ldmatrix helpers ----------
static __device__ __forceinline__ void mma16(float* d, const uint32_t* a,
                                             uint32_t b0, uint32_t b1) {
    asm volatile(
        "mma.sync.aligned.m16n8k16.row.col.f32.bf16.bf16.f32 "
        "{%0,%1,%2,%3}, {%4,%5,%6,%7}, {%8,%9}, {%0,%1,%2,%3};"
        : "+f"(d[0]), "+f"(d[1]), "+f"(d[2]), "+f"(d[3])
        : "r"(a[0]), "r"(a[1]), "r"(a[2]), "r"(a[3]), "r"(b0), "r"(b1));
}
#define LDMX4(r, ad) \
    asm volatile("ldmatrix.sync.aligned.m8n8.x4.shared.b16 {%0,%1,%2,%3}, [%4];" \
        : "=r"((r)[0]), "=r"((r)[1]), "=r"((r)[2]), "=r"((r)[3]) : "r"(ad))
#define LDMX2(r0, r1, ad) \
    asm volatile("ldmatrix.sync.aligned.m8n8.x2.shared.b16 {%0,%1}, [%2];" \
        : "=r"(r0), "=r"(r1) : "r"(ad))

static __device__ __forceinline__ uint32_t packbf(float x, float y) {
    __nv_bfloat162 h = __floats2bfloat162_rn(x, y);
    return *reinterpret_cast<uint32_t*>(&h);
}
static __device__ __forceinline__ void split2(float a, float b, uint32_t& hi, uint32_t& lo) {
    __nv_bfloat16 ha = __float2bfloat16_rn(a), hb = __float2bfloat16_rn(b);
    __nv_bfloat162 p; p.x = ha; p.y = hb;
    hi = *reinterpret_cast<uint32_t*>(&p);
    lo = packbf(a - __bfloat162float(ha), b - __bfloat162float(hb));
}
static __device__ __forceinline__ void split4(float4 v, uint2& hi, uint2& lo) {
    split2(v.x, v.y, hi.x, lo.x);
    split2(v.z, v.w, hi.y, lo.y);
}

#define RSTR 20   // smem row stride in u32

// ---------- bf16x3 GEMM (fp32 inputs): D[m,n]=alpha*sum_k A[m,k]B[n,k] (+bias)(-I) -----
// M%128==0, N = NT*grid.x, K%32==0, batch = grid.z. Double-buffered; ldmatrix frag loads.
template <int NT>
__global__ __launch_bounds__(256, 1) void mma_gemm(
    const float* __restrict__ A, int lda, long sA,
    const float* __restrict__ Bm, int ldb, long sB,
    float* __restrict__ C, int ldc, long sC,
    int K, const float* __restrict__ bias, float alpha, int minusI)
{
    constexpr int NTILES = NT / 16;
    constexpr int NB = NT / 32;
    constexpr int AROWS_U32 = 128 * RSTR;
    constexpr int BROWS_U32 = NT * RSTR;
    constexpr int STG = 2 * AROWS_U32 + 2 * BROWS_U32;

    extern __shared__ uint32_t dsm[];

    A += (long)blockIdx.z * sA; Bm += (long)blockIdx.z * sB; C += (long)blockIdx.z * sC;
    const int m0 = blockIdx.y * 128, n0 = blockIdx.x * NT;
    const int tid = threadIdx.x, wid = tid >> 5, lid = tid & 31;
    const int g = lid >> 2, t = lid & 3;
    const int wm = (wid & 3) * 32, wn = (wid >> 2) * (NT / 2);

    const float* Ag = A + (long)m0 * lda;
    const float* Bg = Bm + (long)n0 * ldb;

    float acc[2][NTILES][4];
    #pragma unroll
    for (int i = 0; i < 2; i++)
        #pragma unroll
        for (int j = 0; j < NTILES; j++)
            #pragma unroll
            for (int q = 0; q < 4; q++) acc[i][j][q] = 0.f;

    const int nch = K >> 5;
    float4 pA[4], pB[NB];

    const uint32_t smem0 = (uint32_t)__cvta_generic_to_shared(dsm);
    // ldmatrix lane byte-offsets (within a stage)
    const uint32_t laneAoff = (((wm + (lid & 15)) * RSTR + ((lid & 16) ? 4 : 0)) << 2);
    const uint32_t laneBoff = (((2 * AROWS_U32) + (wn + (lid & 7)) * RSTR + ((lid & 8) ? 4 : 0)) << 2);

    // prologue: chunk 0
    #pragma unroll
    for (int i = 0; i < 4; i++) {
        int f = i * 256 + tid;
        pA[i] = *(const float4*)(Ag + (long)(f >> 3) * lda + ((f & 7) << 2));
    }
    #pragma unroll
    for (int i = 0; i < NB; i++) {
        int f = i * 256 + tid;
        pB[i] = *(const float4*)(Bg + (long)(f >> 3) * ldb + ((f & 7) << 2));
    }
    {
        uint32_t* Ah = dsm;                 uint32_t* Al = dsm + AROWS_U32;
        uint32_t* Bh = dsm + 2 * AROWS_U32; uint32_t* Bl = Bh + BROWS_U32;
        #pragma unroll
        for (int i = 0; i < 4; i++) {
            int f = i * 256 + tid, row = f >> 3, q = f & 7;
            uint2 hi, lo; split4(pA[i], hi, lo);
            *(uint2*)(Ah + row * RSTR + 2 * q) = hi;
            *(uint2*)(Al + row * RSTR + 2 * q) = lo;
        }
        #pragma unroll
        for (int i = 0; i < NB; i++) {
            int f = i * 256 + tid, row = f >> 3, q = f & 7;
            uint2 hi, lo; split4(pB[i], hi, lo);
            *(uint2*)(Bh + row * RSTR + 2 * q) = hi;
            *(uint2*)(Bl + row * RSTR + 2 * q) = lo;
        }
    }
    __syncthreads();

    for (int c = 0; c < nch; c++) {
        if (c + 1 < nch) {
            const int k0 = (c + 1) << 5;
            #pragma unroll
            for (int i = 0; i < 4; i++) {
                int f = i * 256 + tid;
                pA[i] = *(const float4*)(Ag + (long)(f >> 3) * lda + k0 + ((f & 7) << 2));
            }
            #pragma unroll
            for (int i = 0; i < NB; i++) {
                int f = i * 256 + tid;
                pB[i] = *(const float4*)(Bg + (long)(f >> 3) * ldb + k0 + ((f & 7) << 2));
            }
        }

        // MMA on current stage (ldmatrix fragment loads)
        {
            const uint32_t stB = smem0 + (c & 1) * (STG << 2);
            const uint32_t aA = stB + laneAoff;
            const uint32_t aB = stB + laneBoff;
            #pragma unroll
            for (int s = 0; s < 2; s++) {
                uint32_t ah[2][4], al[2][4];
                #pragma unroll
                for (int mt = 0; mt < 2; mt++) {
                    uint32_t ad = aA + mt * (16 * RSTR * 4) + s * 32;
                    LDMX4(ah[mt], ad);
                    LDMX4(al[mt], ad + AROWS_U32 * 4);
                }
                #pragma unroll
                for (int nt = 0; nt < NTILES; nt++) {
                    uint32_t bd = aB + nt * (8 * RSTR * 4) + s * 32;
                    uint32_t bh0, bh1, bl0, bl1;
                    LDMX2(bh0, bh1, bd);
                    LDMX2(bl0, bl1, bd + BROWS_U32 * 4);
                    #pragma unroll
                    for (int mt = 0; mt < 2; mt++) {
                        mma16(acc[mt][nt], ah[mt], bh0, bh1);
                        mma16(acc[mt][nt], al[mt], bh0, bh1);
                        mma16(acc[mt][nt], ah[mt], bl0, bl1);
                    }
                }
            }
        }

        if (c + 1 < nch) {
            uint32_t* base = dsm + ((c + 1) & 1) * STG;
            uint32_t* Ah = base;                 uint32_t* Al = base + AROWS_U32;
            uint32_t* Bh = base + 2 * AROWS_U32; uint32_t* Bl = Bh + BROWS_U32;
            #pragma unroll
            for (int i = 0; i < 4; i++) {
                int f = i * 256 + tid, row = f >> 3, q = f & 7;
                uint2 hi, lo; split4(pA[i], hi, lo);
                *(uint2*)(Ah + row * RSTR + 2 * q) = hi;
                *(uint2*)(Al + row * RSTR + 2 * q) = lo;
            }
            #pragma unroll
            for (int i = 0; i < NB; i++) {
                int f = i * 256 + tid, row = f >> 3, q = f & 7;
                uint2 hi, lo; split4(pB[i], hi, lo);
                *(uint2*)(Bh + row * RSTR + 2 * q) = hi;
                *(uint2*)(Bl + row * RSTR + 2 * q) = lo;
            }
            __syncthreads();
        }
    }

    // ---- epilogue ----
    #pragma unroll
    for (int mt = 0; mt < 2; mt++) {
        int r0 = m0 + wm + mt * 16 + g;
        #pragma unroll
        for (int nt = 0; nt < NTILES; nt++) {
            int col = n0 + wn + nt * 8 + t * 2;
            float b0 = 0.f, b1 = 0.f;
            if (bias) { b0 = __ldg(&bias[col]); b1 = __ldg(&bias[col + 1]); }
            float d0 = acc[mt][nt][0] * alpha + b0;
            float d1 = acc[mt][nt][1] * alpha + b1;
            float d2 = acc[mt][nt][2] * alpha + b0;
            float d3 = acc[mt][nt][3] * alpha + b1;
            if (minusI) {
                if (r0 == col)         d0 -= 1.0f;
                if (r0 == col + 1)     d1 -= 1.0f;
                if (r0 + 8 == col)     d2 -= 1.0f;
                if (r0 + 8 == col + 1) d3 -= 1.0f;
            }
            *(float2*)(C + (long)r0 * ldc + col)       = make_float2(d0, d1);
            *(float2*)(C + (long)(r0 + 8) * ldc + col) = make_float2(d2, d3);
        }
    }
}

// ---------- weight transpose+split: Wg[n][ki][o] -> WtH/WtL[n][o][ki/2] ----------
template <int O>
__global__ __launch_bounds__(256) void wsplit(const float* __restrict__ W,
                                              uint32_t* __restrict__ WtH,
                                              uint32_t* __restrict__ WtL)
{
    __shared__ float tsm[64][33];
    const int n = blockIdx.x, o0 = blockIdx.y * 32;
    const float* Wn = W + (long)n * KI * O;
    uint32_t* Hn = WtH + (long)n * O * (KI / 2);
    uint32_t* Ln = WtL + (long)n * O * (KI / 2);
    for (int k0 = 0; k0 < KI; k0 += 64) {
        int kt = min(64, KI - k0);
        for (int i = threadIdx.y; i < kt; i += 8)
            tsm[i][threadIdx.x] = Wn[(long)(k0 + i) * O + o0 + threadIdx.x];
        __syncthreads();
        int kp = threadIdx.x;               // ki pair within tile
        if (kp < kt / 2) {
            for (int i = threadIdx.y; i < 32; i += 8) {
                uint32_t h, l;
                split2(tsm[2 * kp][i], tsm[2 * kp + 1][i], h, l);
                long off = (long)(o0 + i) * (KI / 2) + (k0 >> 1) + kp;
                Hn[off] = h; Ln[off] = l;
            }
        }
        __syncthreads();
    }
}

// ---------- per-node contraction on tensor cores ----------
// D[b][o] = sum_ki XG[b*Nn+n][ki] * Wt[n][o][ki] + bias[n][o]; M=64 (b), N=O, K=288.
template <int O>
__global__ __launch_bounds__(256, 1) void pernode_mma(
    const float* __restrict__ XG, const uint32_t* __restrict__ WtH,
    const uint32_t* __restrict__ WtL, const float* __restrict__ bias,
    float* __restrict__ out)
{
    constexpr int NTILES = O / 32;          // per-warp n8 tiles (warp covers O/4)
    constexpr int AR = 64 * RSTR;           // A rows (hi) in u32
    constexpr int BR = O * RSTR;
    __shared__ uint32_t psm[2 * AR + 2 * BR];

    const int n = blockIdx.x, tid = threadIdx.x, wid = tid >> 5, lid = tid & 31;
    const int g = lid >> 2, t = lid & 3;
    const int wm = (wid & 1) * 32, wn = (wid >> 1) * (O / 4);

    const uint32_t* Hn = WtH + (long)n * O * (KI / 2);
    const uint32_t* Ln = WtL + (long)n * O * (KI / 2);

    float acc[2][NTILES][4];
    #pragma unroll
    for (int i = 0; i < 2; i++)
        #pragma unroll
        for (int j = 0; j < NTILES; j++)
            #pragma unroll
            for (int q = 0; q < 4; q++) acc[i][j][q] = 0.f;

    const uint32_t smem0 = (uint32_t)__cvta_generic_to_shared(psm);
    const uint32_t laneAoff = (((wm + (lid & 15)) * RSTR + ((lid & 16) ? 4 : 0)) << 2);
    const uint32_t laneBoff = (((2 * AR) + (wn + (lid & 7)) * RSTR + ((lid & 8) ? 4 : 0)) << 2);

    uint32_t* Ah = psm;          uint32_t* Al = psm + AR;
    uint32_t* Bh = psm + 2 * AR; uint32_t* Bl = Bh + BR;

    for (int c = 0; c < KI / 32; c++) {
        const int k0 = c << 5;
        if (c) __syncthreads();
        // stage A: 64 rows x 32 fp32 -> split
        #pragma unroll
        for (int i = 0; i < 2; i++) {
            int f = i * 256 + tid, row = f >> 3, q = f & 7;
            float4 v = *(const float4*)(XG + ((long)row * Nn + n) * KI + k0 + (q << 2));
            uint2 hi, lo; split4(v, hi, lo);
            *(uint2*)(Ah + row * RSTR + 2 * q) = hi;
            *(uint2*)(Al + row * RSTR + 2 * q) = lo;
        }
        // stage B: O rows x 16 u32 (pre-split)
        #pragma unroll
        for (int i = 0; i < O / 64; i++) {
            int f = i * 256 + tid, row = f >> 2, qc = (f & 3) << 2;
            *(uint4*)(Bh + row * RSTR + qc) = *(const uint4*)(Hn + (long)row * (KI / 2) + (k0 >> 1) + qc);
            *(uint4*)(Bl + row * RSTR + qc) = *(const uint4*)(Ln + (long)row * (KI / 2) + (k0 >> 1) + qc);
        }
        __syncthreads();

        #pragma unroll
        for (int s = 0; s < 2; s++) {
            uint32_t ah[2][4], al[2][4];
            #pragma unroll
            for (int mt = 0; mt < 2; mt++) {
                uint32_t ad = smem0 + laneAoff + mt * (16 * RSTR * 4) + s * 32;
                LDMX4(ah[mt], ad);
                LDMX4(al[mt], ad + AR * 4);
            }
            #pragma unroll
            for (int nt = 0; nt < NTILES; nt++) {
                uint32_t bd = smem0 + laneBoff + nt * (8 * RSTR * 4) + s * 32;
                uint32_t bh0, bh1, bl0, bl1;
                LDMX2(bh0, bh1, bd);
                LDMX2(bl0, bl1, bd + BR * 4);
                #pragma unroll
                for (int mt = 0; mt < 2; mt++) {
                    mma16(acc[mt][nt], ah[mt], bh0, bh1);
                    mma16(acc[mt][nt], al[mt], bh0, bh1);
                    mma16(acc[mt][nt], ah[mt], bl0, bl1);
                }
            }
        }
    }

    #pragma unroll
    for (int mt = 0; mt < 2; mt++) {
        int b = wm + mt * 16 + g;
        #pragma unroll
        for (int nt = 0; nt < NTILES; nt++) {
            int col = wn + nt * 8 + t * 2;
            float b0 = bias[(long)n * O + col], b1 = bias[(long)n * O + col + 1];
            *(float2*)(out + ((long)b * Nn + n) * O + col) =
                make_float2(acc[mt][nt][0] + b0, acc[mt][nt][1] + b1);
            *(float2*)(out + ((long)(b + 8) * Nn + n) * O + col) =
                make_float2(acc[mt][nt][2] + b0, acc[mt][nt][3] + b1);
        }
    }
}

// ---------- small kernels ----------
static __device__ __forceinline__ float lrelu(float v) { return v >= 0.0f ? v : 0.01f * v; }
static __device__ __forceinline__ float sigmoidf(float v) { return 1.0f / (1.0f + expf(-v)); }

__global__ void emb_matmul2(const float* __restrict__ emb, const float* __restrict__ pool,
                            float* __restrict__ out, int C)
{
    __shared__ float esm[32][EDm];
    const int tid = threadIdx.x;
    const int cb = blockIdx.x * 256 + tid;
    const int n0 = blockIdx.y * 32;
    for (int i = tid; i < 32 * EDm; i += 256)
        esm[i >> 4][i & 15] = emb[(n0 + (i >> 4)) * EDm + (i & 15)];
    __syncthreads();
    if (cb >= C) return;
    float p[EDm];
    #pragma unroll
    for (int d = 0; d < EDm; d++) p[d] = pool[(long)d * C + cb];
    #pragma unroll 4
    for (int r = 0; r < 32; r++) {
        float acc = 0.f;
        #pragma unroll
        for (int d = 0; d < EDm; d++) acc += esm[r][d] * p[d];
        out[(long)(n0 + r) * C + cb] = acc;
    }
}

__global__ void transpose_batched(const float* __restrict__ in, long s_in, int ld_in,
                                  float* __restrict__ out, long s_out, int ld_out,
                                  int R, int Cc)
{
    __shared__ float tsm[32][33];
    in  += (long)blockIdx.z * s_in;
    out += (long)blockIdx.z * s_out;
    int r0 = blockIdx.x * 32, c0 = blockIdx.y * 32;
    int c = c0 + threadIdx.x;
    #pragma unroll
    for (int i = 0; i < 32; i += 8) {
        int rr = r0 + threadIdx.y + i;
        if (rr < R && c < Cc) tsm[threadIdx.y + i][threadIdx.x] = in[(long)rr * ld_in + c];
    }
    __syncthreads();
    int rr = r0 + threadIdx.x;
    #pragma unroll
    for (int i = 0; i < 32; i += 8) {
        int cc = c0 + threadIdx.y + i;
        if (cc < Cc && rr < R) out[(long)cc * ld_out + rr] = tsm[threadIdx.x][threadIdx.y + i];
    }
}

__global__ void build_xg0(const float* __restrict__ x, const float* __restrict__ st,
                          float* __restrict__ XG)
{
    long idx = (long)blockIdx.x * blockDim.x + threadIdx.x;
    if (idx >= (long)Bb * Nn * CIN) return;
    int c = (int)(idx % CIN);
    long bn = idx / CIN;
    XG[bn * KI + c] = (c < DIN) ? x[bn * DIN + c] : st[bn * DOUT + (c - DIN)];
}

__global__ void colmean_lrelu(const float* __restrict__ G, float* __restrict__ Y, int C)
{
    int b = blockIdx.x, c = threadIdx.x;
    const float* p = G + (long)b * Nn * C + c;
    float a0 = 0.f, a1 = 0.f, a2 = 0.f, a3 = 0.f;
    for (int n = 0; n < Nn; n += 4) {
        a0 += lrelu(p[(long)(n + 0) * C]); a1 += lrelu(p[(long)(n + 1) * C]);
        a2 += lrelu(p[(long)(n + 2) * C]); a3 += lrelu(p[(long)(n + 3) * C]);
    }
    Y[b * C + c] = (a0 + a1 + a2 + a3) * (1.0f / (float)Nn);
}

__global__ void att_scalar(const float* __restrict__ Y, const float* __restrict__ w1,
                           const float* __restrict__ w2, float* __restrict__ s, int C, int H)
{
    int b = blockIdx.x, j = threadIdx.x;
    float h = 0.f;
    if (j < H) {
        float acc = 0.f;
        for (int c = 0; c < C; c++) acc += Y[b * C + c] * w1[j * C + c];
        h = fmaxf(acc, 0.f) * w2[j];
    }
    #pragma unroll
    for (int off = 16; off; off >>= 1) h += __shfl_down_sync(0xffffffffu, h, off);
    if (j == 0) s[b] = sigmoidf(h);
}

__global__ void gate_combine(const float* __restrict__ G0, const float* __restrict__ G1,
                             const float* __restrict__ s0, const float* __restrict__ s1,
                             const float* __restrict__ x, const float* __restrict__ st,
                             float* __restrict__ XG, float* __restrict__ Rb)
{
    long idx = (long)blockIdx.x * blockDim.x + threadIdx.x;
    if (idx >= (long)Bb * Nn * DOUT) return;
    int o = (int)(idx % DOUT);
    long bn = idx / DOUT;
    int b = (int)(bn >> 10);
    float a0 = s0[b], a1 = s1[b];
    float zi = lrelu(G0[bn * OG + o]) * a0 + lrelu(G1[bn * OG + o]) * a1;
    float ri = lrelu(G0[bn * OG + DOUT + o]) * a0 + lrelu(G1[bn * OG + DOUT + o]) * a1;
    float r = sigmoidf(ri);
    Rb[idx] = r;
    XG[bn * KI + DIN + o] = sigmoidf(zi) * st[idx];
    if (o < DIN) XG[bn * KI + o] = x[bn * DIN + o];
}

__global__ void final_combine(const float* __restrict__ G0u, const float* __restrict__ G1u,
                              const float* __restrict__ t0, const float* __restrict__ t1,
                              const float* __restrict__ Rb, const float* __restrict__ st,
                              float* __restrict__ out)
{
    long idx = (long)blockIdx.x * blockDim.x + threadIdx.x;
    if (idx >= (long)Bb * Nn * DOUT) return;
    long bn = idx / DOUT;
    int b = (int)(bn >> 10);
    float hc = tanhf(lrelu(G0u[idx]) * t0[b] + lrelu(G1u[idx]) * t1[b]);
    float r = Rb[idx];
    out[idx] = r * st[idx] + (1.0f - r) * hc;
}

// ---------- host ----------
static inline int gemm_smem(int NT) { return 2 * (2 * 128 * RSTR + 2 * NT * RSTR) * 4; }

static inline void tc(const float* A, int lda, long sA, const float* Bm, int ldb, long sB,
                      float* C, int ldc, long sC, int M, int N, int NT, int K, int batch,
                      const float* bias, float alpha, int mI)
{
    dim3 grid(N / NT, M / 128, batch);
    int sm = gemm_smem(NT);
    switch (NT) {
    case 128:
        cudaFuncSetAttribute(mma_gemm<128>, cudaFuncAttributeMaxDynamicSharedMemorySize, sm);
        mma_gemm<128><<<grid, 256, sm>>>(A, lda, sA, Bm, ldb, sB, C, ldc, sC, K, bias, alpha, mI);
        break;
    case 96:
        cudaFuncSetAttribute(mma_gemm<96>, cudaFuncAttributeMaxDynamicSharedMemorySize, sm);
        mma_gemm<96><<<grid, 256, sm>>>(A, lda, sA, Bm, ldb, sB, C, ldc, sC, K, bias, alpha, mI);
        break;
    default:
        cudaFuncSetAttribute(mma_gemm<64>, cudaFuncAttributeMaxDynamicSharedMemorySize, sm);
        mma_gemm<64><<<grid, 256, sm>>>(A, lda, sA, Bm, ldb, sB, C, ldc, sC, K, bias, alpha, mI);
        break;
    }
}

extern "C" void kernel_launch(void* const* d_in, const int* in_sizes, int n_in,
                              void* d_out, int out_size)
{
    const float* x     = (const float*)d_in[0];
    const float* state = (const float*)d_in[1];
    const float* emb   = (const float*)d_in[2];
    const float* Lm    = (const float*)d_in[3];
    const float* cheb  = (const float*)d_in[4];
    const float* gwpool = (const float*)d_in[5];
    const float* gbpool = (const float*)d_in[6];
    const float* giw = (const float*)d_in[7];
    const float* gib = (const float*)d_in[8];
    const float* ggw = (const float*)d_in[9];
    const float* ggb = (const float*)d_in[10];
    const float* ga1w1 = (const float*)d_in[11];
    const float* ga1w2 = (const float*)d_in[12];
    const float* ga2w1 = (const float*)d_in[13];
    const float* ga2w2 = (const float*)d_in[14];
    const float* uwpool = (const float*)d_in[15];
    const float* ubpool = (const float*)d_in[16];
    const float* uiw = (const float*)d_in[17];
    const float* uib = (const float*)d_in[18];
    const float* ugw = (const float*)d_in[19];
    const float* ugb = (const float*)d_in[20];
    const float* ua1w1 = (const float*)d_in[21];
    const float* ua1w2 = (const float*)d_in[22];
    const float* ua2w1 = (const float*)d_in[23];
    const float* ua2w2 = (const float*)d_in[24];
    float* out = (float*)d_out;

    float *Wg, *Wu, *bg, *bu, *Lt, *S2, *XG, *Ucm, *X0, *X0T, *XG1;
    float *G0, *G1, *Rb, *Y0, *Y1, *s0, *s1;
    uint32_t *WtgH, *WtgL, *WtuH, *WtuL;
    cudaGetSymbolAddress((void**)&Wg, g_Wg);   cudaGetSymbolAddress((void**)&Wu, g_Wu);
    cudaGetSymbolAddress((void**)&bg, g_bg);   cudaGetSymbolAddress((void**)&bu, g_bu);
    cudaGetSymbolAddress((void**)&Lt, g_Lt);   cudaGetSymbolAddress((void**)&S2, g_S2);
    cudaGetSymbolAddress((void**)&XG, g_XG);   cudaGetSymbolAddress((void**)&Ucm, g_Ucm);
    cudaGetSymbolAddress((void**)&X0, g_X0);   cudaGetSymbolAddress((void**)&X0T, g_X0T);
    cudaGetSymbolAddress((void**)&XG1, g_XG1); cudaGetSymbolAddress((void**)&G0, g_G0);
    cudaGetSymbolAddress((void**)&G1, g_G1);   cudaGetSymbolAddress((void**)&Rb, g_Rb);
    cudaGetSymbolAddress((void**)&Y0, g_Y0);   cudaGetSymbolAddress((void**)&Y1, g_Y1);
    cudaGetSymbolAddress((void**)&s0, g_s0);   cudaGetSymbolAddress((void**)&s1, g_s1);
    cudaGetSymbolAddress((void**)&WtgH, g_WtgH); cudaGetSymbolAddress((void**)&WtgL, g_WtgL);
    cudaGetSymbolAddress((void**)&WtuH, g_WtuH); cudaGetSymbolAddress((void**)&WtuL, g_WtuL);

    const long sXG = (long)Nn * KI;
    dim3 tb(32, 8);

    // per-node weights / biases -> transposed split form
    emb_matmul2<<<dim3(144, 32), 256>>>(emb, gwpool, Wg, KI * OG);
    emb_matmul2<<<dim3(72, 32), 256>>>(emb, uwpool, Wu, KI * OU);
    emb_matmul2<<<dim3(1, 32), 256>>>(emb, gbpool, bg, OG);
    emb_matmul2<<<dim3(1, 32), 256>>>(emb, ubpool, bu, OU);
    wsplit<OG><<<dim3(Nn, OG / 32), tb>>>(Wg, WtgH, WtgL);
    wsplit<OU><<<dim3(Nn, OU / 32), tb>>>(Wu, WtuH, WtuL);

    // S2 = 2*L@L - I  (B operand = L^T, K-major)
    transpose_batched<<<dim3(32, 32, 1), tb>>>(Lm, 0, Nn, Lt, 0, Nn, Nn, Nn);
    tc(Lm, Nn, 0, Lt, Nn, 0, S2, Nn, 0, Nn, Nn, 128, Nn, 1, nullptr, 2.0f, 1);

    for (int phase = 0; phase < 2; phase++) {
        const int O = phase ? OU : OG;
        if (phase == 0)
            build_xg0<<<((long)Bb * Nn * CIN + 255) / 256, 256>>>(x, state, XG);
        transpose_batched<<<dim3(32, 3, Bb), tb>>>(XG, sXG, KI, Ucm, (long)CIN * Nn, Nn, Nn, CIN);
        tc(Lm, Nn, 0, Ucm, Nn, (long)CIN * Nn, XG + CIN,     KI, sXG, Nn, CIN, 96, Nn, Bb, nullptr, 1.0f, 0);
        tc(S2, Nn, 0, Ucm, Nn, (long)CIN * Nn, XG + 2 * CIN, KI, sXG, Nn, CIN, 96, Nn, Bb, nullptr, 1.0f, 0);
        if (phase == 0) pernode_mma<OG><<<Nn, 256>>>(XG, WtgH, WtgL, bg, G0);
        else            pernode_mma<OU><<<Nn, 256>>>(XG, WtuH, WtuL, bu, G0);
        tc(XG, KI, 0, phase ? uiw : giw, CIN, 0, X0, O, 0,
           Bb * Nn, O, phase ? 64 : 128, CIN, 1, phase ? uib : gib, 1.0f, 0);
        transpose_batched<<<dim3(32, O / 32, Bb), tb>>>(X0, (long)Nn * O, O,
                                                        X0T, (long)O * Nn, Nn, Nn, O);
        for (int k = 0; k < KSUP; k++)
            tc(cheb + (long)k * Nn * Nn, Nn, 0, X0T, Nn, (long)O * Nn,
               XG1 + k * O, 3 * O, (long)Nn * 3 * O, Nn, O, phase ? 64 : 128, Nn, Bb, nullptr, 1.0f, 0);
        tc(XG1, 3 * O, 0, phase ? ugw : ggw, 3 * O, 0, G1, O, 0,
           Bb * Nn, O, phase ? 64 : 128, 3 * O, 1, phase ? ugb : ggb, 1.0f, 0);
        colmean_lrelu<<<Bb, O>>>(G0, Y0, O);
        colmean_lrelu<<<Bb, O>>>(G1, Y1, O);
        if (phase == 0) {
            att_scalar<<<Bb, 32>>>(Y0, ga1w1, ga1w2, s0, OG, OG / 16);
            att_scalar<<<Bb, 32>>>(Y1, ga2w1, ga2w2, s1, OG, OG / 16);
            gate_combine<<<((long)Bb * Nn * DOUT + 255) / 256, 256>>>(G0, G1, s0, s1, x, state, XG, Rb);
        } else {
            att_scalar<<<Bb, 32>>>(Y0, ua1w1, ua1w2, s0, OU, OU / 16);
            att_scalar<<<Bb, 32>>>(Y1, ua2w1, ua2w2, s1, OU, OU / 16);
            final_combine<<<((long)Bb * Nn * DOUT + 255) / 256, 256>>>(G0, G1, s0, s1, Rb, state, out);
        }
    }
}

// round 9
// speedup vs baseline: 1.1710x; 1.0658x over previous
#include <cuda_runtime.h>
#include <cuda_bf16.h>
#include <math.h>
#include <stdint.h>

#define Bb   64
#define Nn   1024
#define DIN  32
#define DOUT 64
#define CIN  96
#define KSUP 3
#define EDm  16
#define OG   128
#define OU   64
#define KI   288

__device__ float g_Wg [(size_t)Nn * KI * OG];
__device__ float g_Wu [(size_t)Nn * KI * OU];
__device__ float g_bg [(size_t)Nn * OG];
__device__ float g_bu [(size_t)Nn * OU];
__device__ float g_Lt [(size_t)Nn * Nn];
__device__ float g_LS2[(size_t)2 * Nn * Nn];        // [0]=L copy, [1]=S2
__device__ float g_XG [(size_t)Bb * Nn * KI];
__device__ float g_Ucm[(size_t)Bb * CIN * Nn];
__device__ float g_X0 [(size_t)Bb * Nn * OG];
__device__ float g_X0T[(size_t)Bb * OG * Nn];
__device__ float g_XG1[(size_t)Bb * Nn * 3 * OG];
__device__ float g_G0 [(size_t)Bb * Nn * OG];
__device__ float g_G1 [(size_t)Bb * Nn * OG];
__device__ float g_Rb [(size_t)Bb * Nn * DOUT];
__device__ float g_Y0 [Bb * OG];
__device__ float g_Y1 [Bb * OG];
__device__ float g_s0 [Bb];
__device__ float g_s1 [Bb];
__device__ uint32_t g_WtgH[(size_t)Nn * OG * (KI / 2)], g_WtgL[(size_t)Nn * OG * (KI / 2)];
__device__ uint32_t g_WtuH[(size_t)Nn * OU * (KI / 2)], g_WtuL[(size_t)Nn * OU * (KI / 2)];

// ---------- mma / ldmatrix helpers ----------
static __device__ __forceinline__ void mma16(float* d, const uint32_t* a,
                                             uint32_t b0, uint32_t b1) {
    asm volatile(
        "mma.sync.aligned.m16n8k16.row.col.f32.bf16.bf16.f32 "
        "{%0,%1,%2,%3}, {%4,%5,%6,%7}, {%8,%9}, {%0,%1,%2,%3};"
        : "+f"(d[0]), "+f"(d[1]), "+f"(d[2]), "+f"(d[3])
        : "r"(a[0]), "r"(a[1]), "r"(a[2]), "r"(a[3]), "r"(b0), "r"(b1));
}
#define LDMX4(r, ad) \
    asm volatile("ldmatrix.sync.aligned.m8n8.x4.shared.b16 {%0,%1,%2,%3}, [%4];" \
        : "=r"((r)[0]), "=r"((r)[1]), "=r"((r)[2]), "=r"((r)[3]) : "r"(ad))
#define LDMX2(r0, r1, ad) \
    asm volatile("ldmatrix.sync.aligned.m8n8.x2.shared.b16 {%0,%1}, [%2];" \
        : "=r"(r0), "=r"(r1) : "r"(ad))

static __device__ __forceinline__ uint32_t packbf(float x, float y) {
    __nv_bfloat162 h = __floats2bfloat162_rn(x, y);
    return *reinterpret_cast<uint32_t*>(&h);
}
static __device__ __forceinline__ void split2(float a, float b, uint32_t& hi, uint32_t& lo) {
    __nv_bfloat16 ha = __float2bfloat16_rn(a), hb = __float2bfloat16_rn(b);
    __nv_bfloat162 p; p.x = ha; p.y = hb;
    hi = *reinterpret_cast<uint32_t*>(&p);
    lo = packbf(a - __bfloat162float(ha), b - __bfloat162float(hb));
}
static __device__ __forceinline__ void split4(float4 v, uint2& hi, uint2& lo) {
    split2(v.x, v.y, hi.x, lo.x);
    split2(v.z, v.w, hi.y, lo.y);
}

#define RSTR 20   // smem row stride in u32

// ---------- bf16x3 GEMM with z-decomposition ----------
// blockIdx.z -> z1 = z >> zshift, z0 = z & ((1<<zshift)-1)
// A += z0*sA + z1*sA2 ; B += z0*sB + z1*sB2 ; C += z0*sC + z1*sC2
template <int NT>
__global__ __launch_bounds__(256, 1) void mma_gemm(
    const float* __restrict__ A, int lda, long sA, long sA2,
    const float* __restrict__ Bm, int ldb, long sB, long sB2,
    float* __restrict__ C, int ldc, long sC, long sC2,
    int zshift, int K, const float* __restrict__ bias, float alpha, int minusI)
{
    constexpr int NTILES = NT / 16;
    constexpr int NB = NT / 32;
    constexpr int AROWS_U32 = 128 * RSTR;
    constexpr int BROWS_U32 = NT * RSTR;
    constexpr int STG = 2 * AROWS_U32 + 2 * BROWS_U32;

    extern __shared__ uint32_t dsm[];

    {
        int z = blockIdx.z;
        int z1 = z >> zshift, z0 = z & ((1 << zshift) - 1);
        A  += (long)z0 * sA + (long)z1 * sA2;
        Bm += (long)z0 * sB + (long)z1 * sB2;
        C  += (long)z0 * sC + (long)z1 * sC2;
    }
    const int m0 = blockIdx.y * 128, n0 = blockIdx.x * NT;
    const int tid = threadIdx.x, wid = tid >> 5, lid = tid & 31;
    const int g = lid >> 2, t = lid & 3;
    const int wm = (wid & 3) * 32, wn = (wid >> 2) * (NT / 2);

    const float* Ag = A + (long)m0 * lda;
    const float* Bg = Bm + (long)n0 * ldb;

    float acc[2][NTILES][4];
    #pragma unroll
    for (int i = 0; i < 2; i++)
        #pragma unroll
        for (int j = 0; j < NTILES; j++)
            #pragma unroll
            for (int q = 0; q < 4; q++) acc[i][j][q] = 0.f;

    const int nch = K >> 5;
    float4 pA[4], pB[NB];

    const uint32_t smem0 = (uint32_t)__cvta_generic_to_shared(dsm);
    const uint32_t laneAoff = (((wm + (lid & 15)) * RSTR + ((lid & 16) ? 4 : 0)) << 2);
    const uint32_t laneBoff = (((2 * AROWS_U32) + (wn + (lid & 7)) * RSTR + ((lid & 8) ? 4 : 0)) << 2);

    #pragma unroll
    for (int i = 0; i < 4; i++) {
        int f = i * 256 + tid;
        pA[i] = *(const float4*)(Ag + (long)(f >> 3) * lda + ((f & 7) << 2));
    }
    #pragma unroll
    for (int i = 0; i < NB; i++) {
        int f = i * 256 + tid;
        pB[i] = *(const float4*)(Bg + (long)(f >> 3) * ldb + ((f & 7) << 2));
    }
    {
        uint32_t* Ah = dsm;                 uint32_t* Al = dsm + AROWS_U32;
        uint32_t* Bh = dsm + 2 * AROWS_U32; uint32_t* Bl = Bh + BROWS_U32;
        #pragma unroll
        for (int i = 0; i < 4; i++) {
            int f = i * 256 + tid, row = f >> 3, q = f & 7;
            uint2 hi, lo; split4(pA[i], hi, lo);
            *(uint2*)(Ah + row * RSTR + 2 * q) = hi;
            *(uint2*)(Al + row * RSTR + 2 * q) = lo;
        }
        #pragma unroll
        for (int i = 0; i < NB; i++) {
            int f = i * 256 + tid, row = f >> 3, q = f & 7;
            uint2 hi, lo; split4(pB[i], hi, lo);
            *(uint2*)(Bh + row * RSTR + 2 * q) = hi;
            *(uint2*)(Bl + row * RSTR + 2 * q) = lo;
        }
    }
    __syncthreads();

    for (int c = 0; c < nch; c++) {
        if (c + 1 < nch) {
            const int k0 = (c + 1) << 5;
            #pragma unroll
            for (int i = 0; i < 4; i++) {
                int f = i * 256 + tid;
                pA[i] = *(const float4*)(Ag + (long)(f >> 3) * lda + k0 + ((f & 7) << 2));
            }
            #pragma unroll
            for (int i = 0; i < NB; i++) {
                int f = i * 256 + tid;
                pB[i] = *(const float4*)(Bg + (long)(f >> 3) * ldb + k0 + ((f & 7) << 2));
            }
        }
        {
            const uint32_t stB = smem0 + (c & 1) * (STG << 2);
            const uint32_t aA = stB + laneAoff;
            const uint32_t aB = stB + laneBoff;
            #pragma unroll
            for (int s = 0; s < 2; s++) {
                uint32_t ah[2][4], al[2][4];
                #pragma unroll
                for (int mt = 0; mt < 2; mt++) {
                    uint32_t ad = aA + mt * (16 * RSTR * 4) + s * 32;
                    LDMX4(ah[mt], ad);
                    LDMX4(al[mt], ad + AROWS_U32 * 4);
                }
                #pragma unroll
                for (int nt = 0; nt < NTILES; nt++) {
                    uint32_t bd = aB + nt * (8 * RSTR * 4) + s * 32;
                    uint32_t bh0, bh1, bl0, bl1;
                    LDMX2(bh0, bh1, bd);
                    LDMX2(bl0, bl1, bd + BROWS_U32 * 4);
                    #pragma unroll
                    for (int mt = 0; mt < 2; mt++) {
                        mma16(acc[mt][nt], ah[mt], bh0, bh1);
                        mma16(acc[mt][nt], al[mt], bh0, bh1);
                        mma16(acc[mt][nt], ah[mt], bl0, bl1);
                    }
                }
            }
        }
        if (c + 1 < nch) {
            uint32_t* base = dsm + ((c + 1) & 1) * STG;
            uint32_t* Ah = base;                 uint32_t* Al = base + AROWS_U32;
            uint32_t* Bh = base + 2 * AROWS_U32; uint32_t* Bl = Bh + BROWS_U32;
            #pragma unroll
            for (int i = 0; i < 4; i++) {
                int f = i * 256 + tid, row = f >> 3, q = f & 7;
                uint2 hi, lo; split4(pA[i], hi, lo);
                *(uint2*)(Ah + row * RSTR + 2 * q) = hi;
                *(uint2*)(Al + row * RSTR + 2 * q) = lo;
            }
            #pragma unroll
            for (int i = 0; i < NB; i++) {
                int f = i * 256 + tid, row = f >> 3, q = f & 7;
                uint2 hi, lo; split4(pB[i], hi, lo);
                *(uint2*)(Bh + row * RSTR + 2 * q) = hi;
                *(uint2*)(Bl + row * RSTR + 2 * q) = lo;
            }
            __syncthreads();
        }
    }

    #pragma unroll
    for (int mt = 0; mt < 2; mt++) {
        int r0 = m0 + wm + mt * 16 + g;
        #pragma unroll
        for (int nt = 0; nt < NTILES; nt++) {
            int col = n0 + wn + nt * 8 + t * 2;
            float b0 = 0.f, b1 = 0.f;
            if (bias) { b0 = __ldg(&bias[col]); b1 = __ldg(&bias[col + 1]); }
            float d0 = acc[mt][nt][0] * alpha + b0;
            float d1 = acc[mt][nt][1] * alpha + b1;
            float d2 = acc[mt][nt][2] * alpha + b0;
            float d3 = acc[mt][nt][3] * alpha + b1;
            if (minusI) {
                if (r0 == col)         d0 -= 1.0f;
                if (r0 == col + 1)     d1 -= 1.0f;
                if (r0 + 8 == col)     d2 -= 1.0f;
                if (r0 + 8 == col + 1) d3 -= 1.0f;
            }
            *(float2*)(C + (long)r0 * ldc + col)       = make_float2(d0, d1);
            *(float2*)(C + (long)(r0 + 8) * ldc + col) = make_float2(d2, d3);
        }
    }
}

// ---------- weight transpose+split ----------
template <int O>
__global__ __launch_bounds__(256) void wsplit(const float* __restrict__ W,
                                              uint32_t* __restrict__ WtH,
                                              uint32_t* __restrict__ WtL)
{
    __shared__ float tsm[64][33];
    const int n = blockIdx.x, o0 = blockIdx.y * 32;
    const float* Wn = W + (long)n * KI * O;
    uint32_t* Hn = WtH + (long)n * O * (KI / 2);
    uint32_t* Ln = WtL + (long)n * O * (KI / 2);
    for (int k0 = 0; k0 < KI; k0 += 64) {
        int kt = min(64, KI - k0);
        for (int i = threadIdx.y; i < kt; i += 8)
            tsm[i][threadIdx.x] = Wn[(long)(k0 + i) * O + o0 + threadIdx.x];
        __syncthreads();
        int kp = threadIdx.x;
        if (kp < kt / 2) {
            for (int i = threadIdx.y; i < 32; i += 8) {
                uint32_t h, l;
                split2(tsm[2 * kp][i], tsm[2 * kp + 1][i], h, l);
                long off = (long)(o0 + i) * (KI / 2) + (k0 >> 1) + kp;
                Hn[off] = h; Ln[off] = l;
            }
        }
        __syncthreads();
    }
}

// ---------- per-node contraction on tensor cores ----------
template <int O>
__global__ __launch_bounds__(256, 1) void pernode_mma(
    const float* __restrict__ XG, const uint32_t* __restrict__ WtH,
    const uint32_t* __restrict__ WtL, const float* __restrict__ bias,
    float* __restrict__ out)
{
    constexpr int NTILES = O / 32;
    constexpr int AR = 64 * RSTR;
    constexpr int BR = O * RSTR;
    __shared__ uint32_t psm[2 * AR + 2 * BR];

    const int n = blockIdx.x, tid = threadIdx.x, wid = tid >> 5, lid = tid & 31;
    const int g = lid >> 2, t = lid & 3;
    const int wm = (wid & 1) * 32, wn = (wid >> 1) * (O / 4);

    const uint32_t* Hn = WtH + (long)n * O * (KI / 2);
    const uint32_t* Ln = WtL + (long)n * O * (KI / 2);

    float acc[2][NTILES][4];
    #pragma unroll
    for (int i = 0; i < 2; i++)
        #pragma unroll
        for (int j = 0; j < NTILES; j++)
            #pragma unroll
            for (int q = 0; q < 4; q++) acc[i][j][q] = 0.f;

    const uint32_t smem0 = (uint32_t)__cvta_generic_to_shared(psm);
    const uint32_t laneAoff = (((wm + (lid & 15)) * RSTR + ((lid & 16) ? 4 : 0)) << 2);
    const uint32_t laneBoff = (((2 * AR) + (wn + (lid & 7)) * RSTR + ((lid & 8) ? 4 : 0)) << 2);

    uint32_t* Ah = psm;          uint32_t* Al = psm + AR;
    uint32_t* Bh = psm + 2 * AR; uint32_t* Bl = Bh + BR;

    for (int c = 0; c < KI / 32; c++) {
        const int k0 = c << 5;
        if (c) __syncthreads();
        #pragma unroll
        for (int i = 0; i < 2; i++) {
            int f = i * 256 + tid, row = f >> 3, q = f & 7;
            float4 v = *(const float4*)(XG + ((long)row * Nn + n) * KI + k0 + (q << 2));
            uint2 hi, lo; split4(v, hi, lo);
            *(uint2*)(Ah + row * RSTR + 2 * q) = hi;
            *(uint2*)(Al + row * RSTR + 2 * q) = lo;
        }
        #pragma unroll
        for (int i = 0; i < O / 64; i++) {
            int f = i * 256 + tid, row = f >> 2, qc = (f & 3) << 2;
            *(uint4*)(Bh + row * RSTR + qc) = *(const uint4*)(Hn + (long)row * (KI / 2) + (k0 >> 1) + qc);
            *(uint4*)(Bl + row * RSTR + qc) = *(const uint4*)(Ln + (long)row * (KI / 2) + (k0 >> 1) + qc);
        }
        __syncthreads();

        #pragma unroll
        for (int s = 0; s < 2; s++) {
            uint32_t ah[2][4], al[2][4];
            #pragma unroll
            for (int mt = 0; mt < 2; mt++) {
                uint32_t ad = smem0 + laneAoff + mt * (16 * RSTR * 4) + s * 32;
                LDMX4(ah[mt], ad);
                LDMX4(al[mt], ad + AR * 4);
            }
            #pragma unroll
            for (int nt = 0; nt < NTILES; nt++) {
                uint32_t bd = smem0 + laneBoff + nt * (8 * RSTR * 4) + s * 32;
                uint32_t bh0, bh1, bl0, bl1;
                LDMX2(bh0, bh1, bd);
                LDMX2(bl0, bl1, bd + BR * 4);
                #pragma unroll
                for (int mt = 0; mt < 2; mt++) {
                    mma16(acc[mt][nt], ah[mt], bh0, bh1);
                    mma16(acc[mt][nt], al[mt], bh0, bh1);
                    mma16(acc[mt][nt], ah[mt], bl0, bl1);
                }
            }
        }
    }

    #pragma unroll
    for (int mt = 0; mt < 2; mt++) {
        int b = wm + mt * 16 + g;
        #pragma unroll
        for (int nt = 0; nt < NTILES; nt++) {
            int col = wn + nt * 8 + t * 2;
            float b0 = bias[(long)n * O + col], b1 = bias[(long)n * O + col + 1];
            *(float2*)(out + ((long)b * Nn + n) * O + col) =
                make_float2(acc[mt][nt][0] + b0, acc[mt][nt][1] + b1);
            *(float2*)(out + ((long)(b + 8) * Nn + n) * O + col) =
                make_float2(acc[mt][nt][2] + b0, acc[mt][nt][3] + b1);
        }
    }
}

// ---------- small kernels ----------
static __device__ __forceinline__ float lrelu(float v) { return v >= 0.0f ? v : 0.01f * v; }
static __device__ __forceinline__ float sigmoidf(float v) { return 1.0f / (1.0f + expf(-v)); }

__global__ void emb_matmul2(const float* __restrict__ emb, const float* __restrict__ pool,
                            float* __restrict__ out, int C)
{
    __shared__ float esm[32][EDm];
    const int tid = threadIdx.x;
    const int cb = blockIdx.x * 256 + tid;
    const int n0 = blockIdx.y * 32;
    for (int i = tid; i < 32 * EDm; i += 256)
        esm[i >> 4][i & 15] = emb[(n0 + (i >> 4)) * EDm + (i & 15)];
    __syncthreads();
    if (cb >= C) return;
    float p[EDm];
    #pragma unroll
    for (int d = 0; d < EDm; d++) p[d] = pool[(long)d * C + cb];
    #pragma unroll 4
    for (int r = 0; r < 32; r++) {
        float acc = 0.f;
        #pragma unroll
        for (int d = 0; d < EDm; d++) acc += esm[r][d] * p[d];
        out[(long)(n0 + r) * C + cb] = acc;
    }
}

__global__ void transpose_batched(const float* __restrict__ in, long s_in, int ld_in,
                                  float* __restrict__ out, long s_out, int ld_out,
                                  int R, int Cc)
{
    __shared__ float tsm[32][33];
    in  += (long)blockIdx.z * s_in;
    out += (long)blockIdx.z * s_out;
    int r0 = blockIdx.x * 32, c0 = blockIdx.y * 32;
    int c = c0 + threadIdx.x;
    #pragma unroll
    for (int i = 0; i < 32; i += 8) {
        int rr = r0 + threadIdx.y + i;
        if (rr < R && c < Cc) tsm[threadIdx.y + i][threadIdx.x] = in[(long)rr * ld_in + c];
    }
    __syncthreads();
    int rr = r0 + threadIdx.x;
    #pragma unroll
    for (int i = 0; i < 32; i += 8) {
        int cc = c0 + threadIdx.y + i;
        if (cc < Cc && rr < R) out[(long)cc * ld_out + rr] = tsm[threadIdx.x][threadIdx.y + i];
    }
}

__global__ void build_xg0(const float* __restrict__ x, const float* __restrict__ st,
                          float* __restrict__ XG)
{
    long idx = (long)blockIdx.x * blockDim.x + threadIdx.x;
    if (idx >= (long)Bb * Nn * CIN) return;
    int c = (int)(idx % CIN);
    long bn = idx / CIN;
    XG[bn * KI + c] = (c < DIN) ? x[bn * DIN + c] : st[bn * DOUT + (c - DIN)];
}

__global__ void colmean_lrelu(const float* __restrict__ G, float* __restrict__ Y, int C)
{
    int b = blockIdx.x, c = threadIdx.x;
    const float* p = G + (long)b * Nn * C + c;
    float a0 = 0.f, a1 = 0.f, a2 = 0.f, a3 = 0.f;
    for (int n = 0; n < Nn; n += 4) {
        a0 += lrelu(p[(long)(n + 0) * C]); a1 += lrelu(p[(long)(n + 1) * C]);
        a2 += lrelu(p[(long)(n + 2) * C]); a3 += lrelu(p[(long)(n + 3) * C]);
    }
    Y[b * C + c] = (a0 + a1 + a2 + a3) * (1.0f / (float)Nn);
}

__global__ void att_scalar(const float* __restrict__ Y, const float* __restrict__ w1,
                           const float* __restrict__ w2, float* __restrict__ s, int C, int H)
{
    int b = blockIdx.x, j = threadIdx.x;
    float h = 0.f;
    if (j < H) {
        float acc = 0.f;
        for (int c = 0; c < C; c++) acc += Y[b * C + c] * w1[j * C + c];
        h = fmaxf(acc, 0.f) * w2[j];
    }
    #pragma unroll
    for (int off = 16; off; off >>= 1) h += __shfl_down_sync(0xffffffffu, h, off);
    if (j == 0) s[b] = sigmoidf(h);
}

__global__ void gate_combine(const float* __restrict__ G0, const float* __restrict__ G1,
                             const float* __restrict__ s0, const float* __restrict__ s1,
                             const float* __restrict__ x, const float* __restrict__ st,
                             float* __restrict__ XG, float* __restrict__ Rb)
{
    long idx = (long)blockIdx.x * blockDim.x + threadIdx.x;
    if (idx >= (long)Bb * Nn * DOUT) return;
    int o = (int)(idx % DOUT);
    long bn = idx / DOUT;
    int b = (int)(bn >> 10);
    float a0 = s0[b], a1 = s1[b];
    float zi = lrelu(G0[bn * OG + o]) * a0 + lrelu(G1[bn * OG + o]) * a1;
    float ri = lrelu(G0[bn * OG + DOUT + o]) * a0 + lrelu(G1[bn * OG + DOUT + o]) * a1;
    float r = sigmoidf(ri);
    Rb[idx] = r;
    XG[bn * KI + DIN + o] = sigmoidf(zi) * st[idx];
    if (o < DIN) XG[bn * KI + o] = x[bn * DIN + o];
}

__global__ void final_combine(const float* __restrict__ G0u, const float* __restrict__ G1u,
                              const float* __restrict__ t0, const float* __restrict__ t1,
                              const float* __restrict__ Rb, const float* __restrict__ st,
                              float* __restrict__ out)
{
    long idx = (long)blockIdx.x * blockDim.x + threadIdx.x;
    if (idx >= (long)Bb * Nn * DOUT) return;
    long bn = idx / DOUT;
    int b = (int)(bn >> 10);
    float hc = tanhf(lrelu(G0u[idx]) * t0[b] + lrelu(G1u[idx]) * t1[b]);
    float r = Rb[idx];
    out[idx] = r * st[idx] + (1.0f - r) * hc;
}

// ---------- host ----------
static inline int gemm_smem(int NT) { return 2 * (2 * 128 * RSTR + 2 * NT * RSTR) * 4; }

struct GArgs {
    const float* A; int lda; long sA, sA2;
    const float* B; int ldb; long sB, sB2;
    float* C; int ldc; long sC, sC2;
    int zshift, K; const float* bias; float alpha; int mI;
};
static inline void tc(int M, int N, int NT, int gz, const GArgs& a)
{
    dim3 grid(N / NT, M / 128, gz);
    int sm = gemm_smem(NT);
    switch (NT) {
    case 128:
        cudaFuncSetAttribute(mma_gemm<128>, cudaFuncAttributeMaxDynamicSharedMemorySize, sm);
        mma_gemm<128><<<grid, 256, sm>>>(a.A, a.lda, a.sA, a.sA2, a.B, a.ldb, a.sB, a.sB2,
                                         a.C, a.ldc, a.sC, a.sC2, a.zshift, a.K, a.bias, a.alpha, a.mI);
        break;
    case 96:
        cudaFuncSetAttribute(mma_gemm<96>, cudaFuncAttributeMaxDynamicSharedMemorySize, sm);
        mma_gemm<96><<<grid, 256, sm>>>(a.A, a.lda, a.sA, a.sA2, a.B, a.ldb, a.sB, a.sB2,
                                        a.C, a.ldc, a.sC, a.sC2, a.zshift, a.K, a.bias, a.alpha, a.mI);
        break;
    default:
        cudaFuncSetAttribute(mma_gemm<64>, cudaFuncAttributeMaxDynamicSharedMemorySize, sm);
        mma_gemm<64><<<grid, 256, sm>>>(a.A, a.lda, a.sA, a.sA2, a.B, a.ldb, a.sB, a.sB2,
                                        a.C, a.ldc, a.sC, a.sC2, a.zshift, a.K, a.bias, a.alpha, a.mI);
        break;
    }
}

extern "C" void kernel_launch(void* const* d_in, const int* in_sizes, int n_in,
                              void* d_out, int out_size)
{
    const float* x     = (const float*)d_in[0];
    const float* state = (const float*)d_in[1];
    const float* emb   = (const float*)d_in[2];
    const float* Lm    = (const float*)d_in[3];
    const float* cheb  = (const float*)d_in[4];
    const float* gwpool = (const float*)d_in[5];
    const float* gbpool = (const float*)d_in[6];
    const float* giw = (const float*)d_in[7];
    const float* gib = (const float*)d_in[8];
    const float* ggw = (const float*)d_in[9];
    const float* ggb = (const float*)d_in[10];
    const float* ga1w1 = (const float*)d_in[11];
    const float* ga1w2 = (const float*)d_in[12];
    const float* ga2w1 = (const float*)d_in[13];
    const float* ga2w2 = (const float*)d_in[14];
    const float* uwpool = (const float*)d_in[15];
    const float* ubpool = (const float*)d_in[16];
    const float* uiw = (const float*)d_in[17];
    const float* uib = (const float*)d_in[18];
    const float* ugw = (const float*)d_in[19];
    const float* ugb = (const float*)d_in[20];
    const float* ua1w1 = (const float*)d_in[21];
    const float* ua1w2 = (const float*)d_in[22];
    const float* ua2w1 = (const float*)d_in[23];
    const float* ua2w2 = (const float*)d_in[24];
    float* out = (float*)d_out;

    float *Wg, *Wu, *bg, *bu, *Lt, *LS2, *XG, *Ucm, *X0, *X0T, *XG1;
    float *G0, *G1, *Rb, *Y0, *Y1, *s0, *s1;
    uint32_t *WtgH, *WtgL, *WtuH, *WtuL;
    cudaGetSymbolAddress((void**)&Wg, g_Wg);   cudaGetSymbolAddress((void**)&Wu, g_Wu);
    cudaGetSymbolAddress((void**)&bg, g_bg);   cudaGetSymbolAddress((void**)&bu, g_bu);
    cudaGetSymbolAddress((void**)&Lt, g_Lt);   cudaGetSymbolAddress((void**)&LS2, g_LS2);
    cudaGetSymbolAddress((void**)&XG, g_XG);   cudaGetSymbolAddress((void**)&Ucm, g_Ucm);
    cudaGetSymbolAddress((void**)&X0, g_X0);   cudaGetSymbolAddress((void**)&X0T, g_X0T);
    cudaGetSymbolAddress((void**)&XG1, g_XG1); cudaGetSymbolAddress((void**)&G0, g_G0);
    cudaGetSymbolAddress((void**)&G1, g_G1);   cudaGetSymbolAddress((void**)&Rb, g_Rb);
    cudaGetSymbolAddress((void**)&Y0, g_Y0);   cudaGetSymbolAddress((void**)&Y1, g_Y1);
    cudaGetSymbolAddress((void**)&s0, g_s0);   cudaGetSymbolAddress((void**)&s1, g_s1);
    cudaGetSymbolAddress((void**)&WtgH, g_WtgH); cudaGetSymbolAddress((void**)&WtgL, g_WtgL);
    cudaGetSymbolAddress((void**)&WtuH, g_WtuH); cudaGetSymbolAddress((void**)&WtuL, g_WtuL);

    const long sXG = (long)Nn * KI;
    const long NN = (long)Nn * Nn;
    dim3 tb(32, 8);

    // L copy into combined [L; S2] buffer (D2D async, graph-capturable)
    cudaMemcpyAsync(LS2, Lm, NN * sizeof(float), cudaMemcpyDeviceToDevice);

    // launches 0-2: emb Wg, emb Wu, transpose Lt ; launch 3: S2 GEMM (ncu target)
    emb_matmul2<<<dim3(144, 32), 256>>>(emb, gwpool, Wg, KI * OG);
    emb_matmul2<<<dim3(72, 32), 256>>>(emb, uwpool, Wu, KI * OU);
    transpose_batched<<<dim3(32, 32, 1), tb>>>(Lm, 0, Nn, Lt, 0, Nn, Nn, Nn);
    {
        GArgs a = { Lm, Nn, 0, 0, Lt, Nn, 0, 0, LS2 + NN, Nn, 0, 0,
                    20, Nn, nullptr, 2.0f, 1 };
        tc(Nn, Nn, 128, 1, a);
    }
    emb_matmul2<<<dim3(1, 32), 256>>>(emb, gbpool, bg, OG);
    emb_matmul2<<<dim3(1, 32), 256>>>(emb, ubpool, bu, OU);
    wsplit<OG><<<dim3(Nn, OG / 32), tb>>>(Wg, WtgH, WtgL);
    wsplit<OU><<<dim3(Nn, OU / 32), tb>>>(Wu, WtuH, WtuL);

    for (int phase = 0; phase < 2; phase++) {
        const int O = phase ? OU : OG;
        if (phase == 0)
            build_xg0<<<((long)Bb * Nn * CIN + 255) / 256, 256>>>(x, state, XG);
        transpose_batched<<<dim3(32, 3, Bb), tb>>>(XG, sXG, KI, Ucm, (long)CIN * Nn, Nn, Nn, CIN);
        // merged diffusion: z = s*64 + b, s selects L (0) or S2 (1)
        {
            GArgs a = { LS2, Nn, 0, NN, Ucm, Nn, (long)CIN * Nn, 0,
                        XG + CIN, KI, sXG, CIN, 6, Nn, nullptr, 1.0f, 0 };
            tc(Nn, CIN, 96, 2 * Bb, a);
        }
        if (phase == 0) pernode_mma<OG><<<Nn, 256>>>(XG, WtgH, WtgL, bg, G0);
        else            pernode_mma<OU><<<Nn, 256>>>(XG, WtuH, WtuL, bu, G0);
        {
            GArgs a = { XG, KI, 0, 0, phase ? uiw : giw, CIN, 0, 0, X0, O, 0, 0,
                        20, CIN, phase ? uib : gib, 1.0f, 0 };
            tc(Bb * Nn, O, phase ? 64 : 128, 1, a);
        }
        transpose_batched<<<dim3(32, O / 32, Bb), tb>>>(X0, (long)Nn * O, O,
                                                        X0T, (long)O * Nn, Nn, Nn, O);
        // merged cheb: z = kk*64 + b
        {
            GArgs a = { cheb, Nn, 0, NN, X0T, Nn, (long)O * Nn, 0,
                        XG1, 3 * O, (long)Nn * 3 * O, O, 6, Nn, nullptr, 1.0f, 0 };
            tc(Nn, O, phase ? 64 : 128, KSUP * Bb, a);
        }
        {
            GArgs a = { XG1, 3 * O, 0, 0, phase ? ugw : ggw, 3 * O, 0, 0, G1, O, 0, 0,
                        20, 3 * O, phase ? ugb : ggb, 1.0f, 0 };
            tc(Bb * Nn, O, phase ? 64 : 128, 1, a);
        }
        colmean_lrelu<<<Bb, O>>>(G0, Y0, O);
        colmean_lrelu<<<Bb, O>>>(G1, Y1, O);
        if (phase == 0) {
            att_scalar<<<Bb, 32>>>(Y0, ga1w1, ga1w2, s0, OG, OG / 16);
            att_scalar<<<Bb, 32>>>(Y1, ga2w1, ga2w2, s1, OG, OG / 16);
            gate_combine<<<((long)Bb * Nn * DOUT + 255) / 256, 256>>>(G0, G1, s0, s1, x, state, XG, Rb);
        } else {
            att_scalar<<<Bb, 32>>>(Y0, ua1w1, ua1w2, s0, OU, OU / 16);
            att_scalar<<<Bb, 32>>>(Y1, ua2w1, ua2w2, s1, OU, OU / 16);
            final_combine<<<((long)Bb * Nn * DOUT + 255) / 256, 256>>>(G0, G1, s0, s1, Rb, state, out);
        }
    }
}